// round 12
// baseline (speedup 1.0000x reference)
#include <cuda_runtime.h>
#include <cstdint>

#define RELS 3
#define NMAX 50000
#define HD   256      // H = HF*AH
#define KIN  128      // in_feats

typedef unsigned long long ull;

// ---------------- scratch (static device globals; no allocation) ----------------
__device__ float g_hw   [(size_t)RELS * NMAX * HD];   // 153.6 MB
__device__ float g_num  [(size_t)NMAX * RELS * HD];   // 153.6 MB (concat layout [N, 768])
__device__ float g_denom[(size_t)RELS * NMAX * 4];    // [r][n][head]
__device__ float g_rcp  [(size_t)NMAX * 12];          // [n][r*4+a] reciprocal of denom
__device__ float g_p1   [NMAX];
__device__ float g_p2   [NMAX];
__device__ float g_qs   [(size_t)RELS * NMAX * 4];
__device__ float g_qd   [(size_t)RELS * NMAX * 4];
__device__ float g_U    [32 * KIN];                   // folded projection vectors [col][k]
__device__ float g_Uc   [32];                         // folded constants per col

// ---------------- helpers ----------------
__device__ __forceinline__ void red_add_v4(float* p, float x, float y, float z, float w) {
    asm volatile("red.global.add.v4.f32 [%0], {%1, %2, %3, %4};"
                 :: "l"(p), "f"(x), "f"(y), "f"(z), "f"(w) : "memory");
}
__device__ __forceinline__ ull pack2(float lo, float hi) {
    ull r;
    asm("mov.b64 %0, {%1, %2};" : "=l"(r) : "f"(lo), "f"(hi));
    return r;
}
__device__ __forceinline__ void unpack2(ull v, float& lo, float& hi) {
    asm("mov.b64 {%0, %1}, %2;" : "=f"(lo), "=f"(hi) : "l"(v));
}
// packed dual FMA: d = a * b + d (2x fp32 per issue slot; Blackwell FFMA2)
__device__ __forceinline__ void ffma2(ull& d, ull a, ull b) {
    asm("fma.rn.f32x2 %0, %1, %2, %0;" : "+l"(d) : "l"(a), "l"(b));
}

// ---------------- zero-init kernels ----------------
__global__ void zero_num_kernel(size_t n4) {
    size_t i = (size_t)blockIdx.x * blockDim.x + threadIdx.x;
    if (i < n4) reinterpret_cast<float4*>(g_num)[i] = make_float4(0.f, 0.f, 0.f, 0.f);
}
__global__ void zero_den_kernel(int n) {
    int i = blockIdx.x * blockDim.x + threadIdx.x;
    if (i < n) g_denom[i] = 0.f;
}

// =====================================================================
// Fold all per-node scalar projections into U[32][128]:
//   col 0 : dW @ (fW[0:256]+fW[512:768])          -> p1
//   col 1 : dW @ (fW[256:512]-fW[512:768])        -> p2
//   col 2+c   (c=r*4+a) : wW[r][:,a*64:+64] @ aW[r][0:64]    -> qs
//   col 14+c  (c=r*4+a) : wW[r][:,a*64:+64] @ aW[r][64:128]  -> qd
// =====================================================================
__global__ void prep_U_kernel(const float* __restrict__ dW, const float* __restrict__ fW,
                              const float* __restrict__ wW, const float* __restrict__ aW)
{
    int col = blockIdx.x;     // 0..31
    int k   = threadIdx.x;    // 0..127
    float s = 0.f;
    if (col < 2) {
        const float* dwr = dW + (size_t)k * HD;
        for (int j = 0; j < HD; j++) {
            float f = (col == 0) ? (fW[j] + fW[512 + j]) : (fW[256 + j] - fW[512 + j]);
            s += dwr[j] * f;
        }
    } else if (col < 26) {
        int c = col - 2;
        int half = 0;
        if (c >= 12) { c -= 12; half = 1; }
        int r = c >> 2, a = c & 3;
        const float* wwr = wW + ((size_t)r * KIN + k) * HD + a * 64;
        const float* awr = aW + r * 128 + half * 64;
        for (int j = 0; j < 64; j++) s += wwr[j] * awr[j];
    }
    g_U[col * KIN + k] = s;
}

// one warp per column, lanes reduce over j
__global__ void prep_Uc_kernel(const float* __restrict__ db, const float* __restrict__ fW,
                               const float* __restrict__ wb, const float* __restrict__ aW)
{
    int col  = threadIdx.x >> 5;   // 0..31 (blockDim = 1024)
    int lane = threadIdx.x & 31;
    float s = 0.f;
    if (col < 2) {
        for (int j = lane; j < HD; j += 32) {
            float f = (col == 0) ? (fW[j] + fW[512 + j]) : (fW[256 + j] - fW[512 + j]);
            s += db[j] * f;
        }
    } else if (col < 26) {
        int c = col - 2;
        int half = 0;
        if (c >= 12) { c -= 12; half = 1; }
        int r = c >> 2, a = c & 3;
        for (int j = lane; j < 64; j += 32)
            s += wb[r * HD + a * 64 + j] * aW[r * 128 + half * 64 + j];
    }
#pragma unroll
    for (int o = 16; o > 0; o >>= 1) s += __shfl_xor_sync(0xFFFFFFFFu, s, o);
    if (lane == 0) g_Uc[col] = s;
}

// =====================================================================
// Node scalars from h directly: one warp per node, lane = column.
// =====================================================================
__global__ __launch_bounds__(256) void node_scalars_kernel(const float* __restrict__ h, int N)
{
    __shared__ float sh[8][KIN];
    const int tid  = threadIdx.x;
    const int node0 = blockIdx.x * 8;

    {
        int row = tid >> 5;
        int w4  = tid & 31;
        int n = node0 + row;
        float4 v = make_float4(0.f, 0.f, 0.f, 0.f);
        if (n < N) v = *reinterpret_cast<const float4*>(h + (size_t)n * KIN + w4 * 4);
        *reinterpret_cast<float4*>(&sh[row][w4 * 4]) = v;
    }
    __syncthreads();

    const int w    = tid >> 5;
    const int lane = tid & 31;
    const int n    = node0 + w;
    if (n >= N || lane >= 26) return;

    const float4* urow = reinterpret_cast<const float4*>(g_U + lane * KIN);
    const float4* hrow = reinterpret_cast<const float4*>(&sh[w][0]);
    float acc = 0.f;
#pragma unroll
    for (int q = 0; q < 32; q++) {
        float4 hv = hrow[q];
        float4 uv = urow[q];
        acc += hv.x * uv.x + hv.y * uv.y + hv.z * uv.z + hv.w * uv.w;
    }
    acc += g_Uc[lane];

    if (lane == 0)      g_p1[n] = acc;
    else if (lane == 1) g_p2[n] = acc;
    else if (lane < 14) {
        int c = lane - 2, r = c >> 2, a = c & 3;
        g_qs[((size_t)r * N + n) * 4 + a] = acc;
    } else {
        int c = lane - 14, r = c >> 2, a = c & 3;
        g_qd[((size_t)r * N + n) * 4 + a] = acc;
    }
}

// =====================================================================
// Tiled fp32 GEMM, FFMA2 + 8x8 microtile: C = (scale ⊙ A) @ B + bias
// BM=128, BN=64, BK=16, 128 threads (4 warps), single-buffered smem.
// Per k-step per thread: 4x LDS.128 feed 64 FLOP (32 FFMA2).
// blockIdx.z batches over B/bias/C with the given strides.
// SCALED: A row m, k-block (64-wide) scaled by rowScale[m*12 + (k>>6)].
// =====================================================================
#define GBM 128
#define GBN 64
#define GBK 16
template <bool SCALED>
__global__ __launch_bounds__(128, 4) void gemm_bias_kernel(
    const float* __restrict__ A, const float* __restrict__ B,
    const float* __restrict__ bias, float* __restrict__ C,
    int M, int N, int K, const float* __restrict__ rowScale,
    size_t bStride, size_t biasStride, size_t cStride)
{
    const int z = blockIdx.z;
    B    += (size_t)z * bStride;
    bias += (size_t)z * biasStride;
    C    += (size_t)z * cStride;

    __shared__ float As[GBK][GBM + 4];
    __shared__ float Bs[GBK][GBN];

    const int tid = threadIdx.x;
    const int tx  = tid & 7;          // col group: 8 cols each
    const int ty  = tid >> 3;         // row group: 0..15, 8 rows each
    const int block_m = blockIdx.y * GBM;
    const int block_n = blockIdx.x * GBN;

    // accumulators: 8 rows x 4 packed f32x2 col-pairs = 64 fp32-equiv... (8x8 fp32)
    ull acc2[8][4];
    const ull z2 = pack2(0.f, 0.f);
#pragma unroll
    for (int i = 0; i < 8; i++)
#pragma unroll
        for (int j = 0; j < 4; j++) acc2[i][j] = z2;

    const int b_row = tid >> 4;            // 0..7 (second half +8)
    const int b_col = (tid & 15) << 2;     // 0..60

    for (int k0 = 0; k0 < K; k0 += GBK) {
        // A tile: 128x16 = 512 float4, 4 per thread
#pragma unroll
        for (int i = 0; i < 4; i++) {
            int f   = tid + i * 128;
            int row = f >> 2;
            int kq  = (f & 3) << 2;
            int gm  = block_m + row;
            float4 av = make_float4(0.f, 0.f, 0.f, 0.f);
            if (gm < M) {
                av = *reinterpret_cast<const float4*>(A + (size_t)gm * K + k0 + kq);
                if (SCALED) {
                    float s = __ldg(rowScale + gm * 12 + ((k0 + kq) >> 6));
                    av.x *= s; av.y *= s; av.z *= s; av.w *= s;
                }
            }
            As[kq + 0][row] = av.x;
            As[kq + 1][row] = av.y;
            As[kq + 2][row] = av.z;
            As[kq + 3][row] = av.w;
        }
        // B tile: 16x64 = 256 float4, 2 per thread
        {
            float4 bv0 = *reinterpret_cast<const float4*>(B + (size_t)(k0 + b_row)     * N + block_n + b_col);
            float4 bv1 = *reinterpret_cast<const float4*>(B + (size_t)(k0 + b_row + 8) * N + block_n + b_col);
            *reinterpret_cast<float4*>(&Bs[b_row][b_col])     = bv0;
            *reinterpret_cast<float4*>(&Bs[b_row + 8][b_col]) = bv1;
        }
        __syncthreads();

#pragma unroll
        for (int k = 0; k < GBK; k++) {
            float4 a0 = *reinterpret_cast<const float4*>(&As[k][ty * 8]);
            float4 a1 = *reinterpret_cast<const float4*>(&As[k][ty * 8 + 4]);
            float4 b0 = *reinterpret_cast<const float4*>(&Bs[k][tx * 8]);
            float4 b1 = *reinterpret_cast<const float4*>(&Bs[k][tx * 8 + 4]);
            ull bp[4] = {pack2(b0.x, b0.y), pack2(b0.z, b0.w),
                         pack2(b1.x, b1.y), pack2(b1.z, b1.w)};
            float ra[8] = {a0.x, a0.y, a0.z, a0.w, a1.x, a1.y, a1.z, a1.w};
#pragma unroll
            for (int i = 0; i < 8; i++) {
                ull ad = pack2(ra[i], ra[i]);
                ffma2(acc2[i][0], ad, bp[0]);
                ffma2(acc2[i][1], ad, bp[1]);
                ffma2(acc2[i][2], ad, bp[2]);
                ffma2(acc2[i][3], ad, bp[3]);
            }
        }
        __syncthreads();
    }

    // epilogue: 8 rows x 8 cols
    const int n0 = block_n + tx * 8;
    float4 bb0 = *reinterpret_cast<const float4*>(bias + n0);
    float4 bb1 = *reinterpret_cast<const float4*>(bias + n0 + 4);
#pragma unroll
    for (int i = 0; i < 8; i++) {
        int m = block_m + ty * 8 + i;
        if (m >= M) continue;
        float4 o0, o1;
        unpack2(acc2[i][0], o0.x, o0.y);
        unpack2(acc2[i][1], o0.z, o0.w);
        unpack2(acc2[i][2], o1.x, o1.y);
        unpack2(acc2[i][3], o1.z, o1.w);
        o0.x += bb0.x; o0.y += bb0.y; o0.z += bb0.z; o0.w += bb0.w;
        o1.x += bb1.x; o1.y += bb1.y; o1.z += bb1.z; o1.w += bb1.w;
        *reinterpret_cast<float4*>(C + (size_t)m * N + n0)     = o0;
        *reinterpret_cast<float4*>(C + (size_t)m * N + n0 + 4) = o1;
    }
}

// ---------------- edge kernel: one warp per edge ----------------
__global__ __launch_bounds__(256) void edge_kernel(
    const int* __restrict__ src, const int* __restrict__ dst,
    int r, const float* __restrict__ fb, const float* __restrict__ abr,
    int E, int N)
{
    int warp = (blockIdx.x * blockDim.x + threadIdx.x) >> 5;
    int lane = threadIdx.x & 31;
    if (warp >= E) return;

    const int s = __ldg(src + warp);
    const int d = __ldg(dst + warp);

    float score = g_p1[s] + g_p2[d] + fb[0];
    float sgn = (score > 0.f) ? 1.f : ((score < 0.f) ? -1.f : 0.f);

    const float* qsr = g_qs + (size_t)r * N * 4;
    const float* qdr = g_qd + (size_t)r * N * 4;
    int a = lane >> 3;
    float x = sgn * qsr[s * 4 + a] + qdr[d * 4 + a] + abr[0];
    float alpha = (x > 0.f) ? x : 0.01f * x;
    float ex = expf(alpha);

    if ((lane & 7) == 0)
        atomicAdd(g_denom + ((size_t)r * N + d) * 4 + a, ex);

    float v = ex * sgn;
    const float4* hrow = reinterpret_cast<const float4*>(g_hw + ((size_t)r * N + s) * HD) + lane * 2;
    float4 h0 = hrow[0];
    float4 h1 = hrow[1];
    float* out = g_num + (size_t)d * (RELS * HD) + r * HD + lane * 8;
    red_add_v4(out,     v * h0.x, v * h0.y, v * h0.z, v * h0.w);
    red_add_v4(out + 4, v * h1.x, v * h1.y, v * h1.z, v * h1.w);
}

// ---------------- reciprocal table: g_rcp[n*12 + r*4 + a] ----------------
__global__ void rcp_kernel(int N) {
    int i = blockIdx.x * blockDim.x + threadIdx.x;
    if (i >= N * 12) return;
    int n = i / 12;
    int c = i - n * 12;
    int r = c >> 2;
    int a = c & 3;
    float den = g_denom[((size_t)r * N + n) * 4 + a];
    g_rcp[i] = (den > 0.f) ? (1.f / den) : 0.f;
}

// ---------------- launch ----------------
extern "C" void kernel_launch(void* const* d_in, const int* in_sizes, int n_in,
                              void* d_out, int out_size)
{
    const float* h    = (const float*)d_in[0];
    const float* dW   = (const float*)d_in[1];
    const float* db   = (const float*)d_in[2];
    const float* fW   = (const float*)d_in[3];
    const float* fb   = (const float*)d_in[4];
    const float* wW   = (const float*)d_in[5];
    const float* wb   = (const float*)d_in[6];
    const float* aW   = (const float*)d_in[7];
    const float* ab   = (const float*)d_in[8];
    const float* linW = (const float*)d_in[9];
    const float* linb = (const float*)d_in[10];
    const int*   src  = (const int*)d_in[11];
    const int*   dst  = (const int*)d_in[12];

    const int N = in_sizes[0] / KIN;        // 50000
    const int E = in_sizes[11] / RELS;      // 300000

    float *p_hw, *p_num, *p_rcp;
    cudaGetSymbolAddress((void**)&p_hw,  g_hw);
    cudaGetSymbolAddress((void**)&p_num, g_num);
    cudaGetSymbolAddress((void**)&p_rcp, g_rcp);

    // zero accumulators
    {
        size_t n4 = (size_t)N * (RELS * HD) / 4;
        zero_num_kernel<<<(unsigned)((n4 + 255) / 256), 256>>>(n4);
        int nd = RELS * N * 4;
        zero_den_kernel<<<(nd + 255) / 256, 256>>>(nd);
    }

    // folded projection vectors + constants
    prep_U_kernel<<<32, 128>>>(dW, fW, wW, aW);
    prep_Uc_kernel<<<1, 1024>>>(db, fW, wb, aW);

    // hw_r = h @ wW[r] + wb[r]  — batched over blockIdx.z
    {
        dim3 ggrid(HD / GBN, (N + GBM - 1) / GBM, RELS);   // (4, 391, 3)
        gemm_bias_kernel<false><<<ggrid, 128>>>(
            h, wW, wb, p_hw, N, HD, KIN, nullptr,
            (size_t)KIN * HD, (size_t)HD, (size_t)N * HD);
    }

    // per-node scalars straight from h
    node_scalars_kernel<<<(N + 7) / 8, 256>>>(h, N);

    // edge aggregation per relation
    for (int r = 0; r < RELS; r++)
        edge_kernel<<<(E + 7) / 8, 256>>>(src + (size_t)r * E, dst + (size_t)r * E,
                                          r, fb, ab + r, E, N);

    // reciprocal of softmax denominators (folded into final GEMM A-load)
    rcp_kernel<<<(N * 12 + 255) / 256, 256>>>(N);

    // out = (rcp ⊙ num) @ linW + linb
    {
        dim3 ggrid(HD / GBN, (N + GBM - 1) / GBM, 1);
        gemm_bias_kernel<true><<<ggrid, 128>>>(
            p_num, linW, linb, (float*)d_out, N, HD, RELS * HD, p_rcp, 0, 0, 0);
    }
}

// round 13
// speedup vs baseline: 1.1439x; 1.1439x over previous
#include <cuda_runtime.h>
#include <cstdint>

#define RELS 3
#define NMAX 50000
#define EMAX 300000
#define HD   256      // H = HF*AH
#define KIN  128      // in_feats

typedef unsigned long long ull;

// ---------------- scratch (static device globals; no allocation) ----------------
__device__ float g_hw  [(size_t)RELS * NMAX * HD];   // 153.6 MB
__device__ float g_num [(size_t)NMAX * RELS * HD];   // 153.6 MB (concat layout [N, 768])
__device__ float g_p1  [NMAX];
__device__ float g_p2  [NMAX];
__device__ float g_qs  [(size_t)RELS * NMAX * 4];
__device__ float g_qd  [(size_t)RELS * NMAX * 4];
__device__ float g_U   [32 * KIN];                   // folded projection vectors [col][k]
__device__ float g_Uc  [32];                         // folded constants per col
// CSR scratch
__device__ int g_cnt [RELS * NMAX];
__device__ int g_cur [RELS * NMAX];
__device__ int g_off [RELS * (NMAX + 1)];
__device__ int g_esrc[(size_t)RELS * EMAX];

// ---------------- helpers ----------------
__device__ __forceinline__ ull pack2(float lo, float hi) {
    ull r;
    asm("mov.b64 %0, {%1, %2};" : "=l"(r) : "f"(lo), "f"(hi));
    return r;
}
__device__ __forceinline__ void unpack2(ull v, float& lo, float& hi) {
    asm("mov.b64 {%0, %1}, %2;" : "=f"(lo), "=f"(hi) : "l"(v));
}
// packed dual FMA: d = a * b + d (2x fp32 per issue slot; Blackwell FFMA2)
__device__ __forceinline__ void ffma2(ull& d, ull a, ull b) {
    asm("fma.rn.f32x2 %0, %1, %2, %0;" : "+l"(d) : "l"(a), "l"(b));
}

// =====================================================================
// Fold all per-node scalar projections into U[32][128]:
//   col 0 : dW @ (fW[0:256]+fW[512:768])          -> p1
//   col 1 : dW @ (fW[256:512]-fW[512:768])        -> p2
//   col 2+c   (c=r*4+a) : wW[r][:,a*64:+64] @ aW[r][0:64]    -> qs
//   col 14+c  (c=r*4+a) : wW[r][:,a*64:+64] @ aW[r][64:128]  -> qd
// =====================================================================
__global__ void prep_U_kernel(const float* __restrict__ dW, const float* __restrict__ fW,
                              const float* __restrict__ wW, const float* __restrict__ aW)
{
    int col = blockIdx.x;     // 0..31
    int k   = threadIdx.x;    // 0..127
    float s = 0.f;
    if (col < 2) {
        const float* dwr = dW + (size_t)k * HD;
        for (int j = 0; j < HD; j++) {
            float f = (col == 0) ? (fW[j] + fW[512 + j]) : (fW[256 + j] - fW[512 + j]);
            s += dwr[j] * f;
        }
    } else if (col < 26) {
        int c = col - 2;
        int half = 0;
        if (c >= 12) { c -= 12; half = 1; }
        int r = c >> 2, a = c & 3;
        const float* wwr = wW + ((size_t)r * KIN + k) * HD + a * 64;
        const float* awr = aW + r * 128 + half * 64;
        for (int j = 0; j < 64; j++) s += wwr[j] * awr[j];
    }
    g_U[col * KIN + k] = s;
}

// one warp per column, lanes reduce over j
__global__ void prep_Uc_kernel(const float* __restrict__ db, const float* __restrict__ fW,
                               const float* __restrict__ wb, const float* __restrict__ aW)
{
    int col  = threadIdx.x >> 5;   // 0..31 (blockDim = 1024)
    int lane = threadIdx.x & 31;
    float s = 0.f;
    if (col < 2) {
        for (int j = lane; j < HD; j += 32) {
            float f = (col == 0) ? (fW[j] + fW[512 + j]) : (fW[256 + j] - fW[512 + j]);
            s += db[j] * f;
        }
    } else if (col < 26) {
        int c = col - 2;
        int half = 0;
        if (c >= 12) { c -= 12; half = 1; }
        int r = c >> 2, a = c & 3;
        for (int j = lane; j < 64; j += 32)
            s += wb[r * HD + a * 64 + j] * aW[r * 128 + half * 64 + j];
    }
#pragma unroll
    for (int o = 16; o > 0; o >>= 1) s += __shfl_xor_sync(0xFFFFFFFFu, s, o);
    if (lane == 0) g_Uc[col] = s;
}

// =====================================================================
// Node scalars from h directly: one warp per node, lane = column.
// =====================================================================
__global__ __launch_bounds__(256) void node_scalars_kernel(const float* __restrict__ h, int N)
{
    __shared__ float sh[8][KIN];
    const int tid  = threadIdx.x;
    const int node0 = blockIdx.x * 8;

    {
        int row = tid >> 5;
        int w4  = tid & 31;
        int n = node0 + row;
        float4 v = make_float4(0.f, 0.f, 0.f, 0.f);
        if (n < N) v = *reinterpret_cast<const float4*>(h + (size_t)n * KIN + w4 * 4);
        *reinterpret_cast<float4*>(&sh[row][w4 * 4]) = v;
    }
    __syncthreads();

    const int w    = tid >> 5;
    const int lane = tid & 31;
    const int n    = node0 + w;
    if (n >= N || lane >= 26) return;

    const float4* urow = reinterpret_cast<const float4*>(g_U + lane * KIN);
    const float4* hrow = reinterpret_cast<const float4*>(&sh[w][0]);
    float acc = 0.f;
#pragma unroll
    for (int q = 0; q < 32; q++) {
        float4 hv = hrow[q];
        float4 uv = urow[q];
        acc += hv.x * uv.x + hv.y * uv.y + hv.z * uv.z + hv.w * uv.w;
    }
    acc += g_Uc[lane];

    if (lane == 0)      g_p1[n] = acc;
    else if (lane == 1) g_p2[n] = acc;
    else if (lane < 14) {
        int c = lane - 2, r = c >> 2, a = c & 3;
        g_qs[((size_t)r * N + n) * 4 + a] = acc;
    } else {
        int c = lane - 14, r = c >> 2, a = c & 3;
        g_qd[((size_t)r * N + n) * 4 + a] = acc;
    }
}

// =====================================================================
// CSR construction: count -> scan -> scatter
// =====================================================================
__global__ void zero_cnt_kernel(int n) {
    int i = blockIdx.x * blockDim.x + threadIdx.x;
    if (i < n) g_cnt[i] = 0;
}

__global__ void count_kernel(const int* __restrict__ dst, int E, int N) {
    int r = blockIdx.y;
    int e = blockIdx.x * blockDim.x + threadIdx.x;
    if (e >= E) return;
    int d = __ldg(dst + (size_t)r * E + e);
    atomicAdd(g_cnt + r * N + d, 1);
}

// one block (1024 threads) per relation: exclusive scan of counts -> offsets
__global__ __launch_bounds__(1024) void scan_kernel(int N) {
    const int r    = blockIdx.x;
    const int tid  = threadIdx.x;
    const int lane = tid & 31, wid = tid >> 5;
    __shared__ int wsum[32];
    __shared__ int carry;
    if (tid == 0) carry = 0;
    __syncthreads();
    const int* cnt = g_cnt + r * N;
    int* off = g_off + r * (N + 1);
    for (int base = 0; base < N; base += 1024) {
        int i = base + tid;
        int v = (i < N) ? cnt[i] : 0;
        int x = v;
#pragma unroll
        for (int o = 1; o < 32; o <<= 1) {
            int y = __shfl_up_sync(0xFFFFFFFFu, x, o);
            if (lane >= o) x += y;
        }
        if (lane == 31) wsum[wid] = x;
        __syncthreads();
        if (wid == 0) {
            int y = wsum[lane];
#pragma unroll
            for (int o = 1; o < 32; o <<= 1) {
                int z = __shfl_up_sync(0xFFFFFFFFu, y, o);
                if (lane >= o) y += z;
            }
            wsum[lane] = y;
        }
        __syncthreads();
        int prefix = (wid > 0) ? wsum[wid - 1] : 0;
        int c = carry;
        if (i < N) off[i] = c + prefix + x - v;
        int total = wsum[31];
        __syncthreads();
        if (tid == 0) carry = c + total;
        __syncthreads();
    }
    if (tid == 0) off[N] = carry;
}

__global__ void copy_cur_kernel(int N) {
    int i = blockIdx.x * blockDim.x + threadIdx.x;
    if (i >= RELS * N) return;
    int r = i / N, n = i - r * N;
    g_cur[i] = g_off[r * (N + 1) + n];
}

__global__ void scatter_kernel(const int* __restrict__ src, const int* __restrict__ dst,
                               int E, int N) {
    int r = blockIdx.y;
    int e = blockIdx.x * blockDim.x + threadIdx.x;
    if (e >= E) return;
    int d = __ldg(dst + (size_t)r * E + e);
    int pos = atomicAdd(g_cur + r * N + d, 1);
    g_esrc[(size_t)r * E + pos] = __ldg(src + (size_t)r * E + e);
}

// =====================================================================
// Gather: one warp per (dst node, relation). Register accumulation of the
// 256-wide numerator + in-register softmax denominator; normalized single
// write to g_num. No atomics, no zero-init, no rcp pass.
// =====================================================================
__global__ __launch_bounds__(256) void gather_kernel(
    const float* __restrict__ fb, const float* __restrict__ ab, int E, int N)
{
    const int r    = blockIdx.y;
    const int d    = blockIdx.x * 8 + (threadIdx.x >> 5);
    const int lane = threadIdx.x & 31;
    if (d >= N) return;

    const int* off = g_off + r * (N + 1);
    const int beg = off[d], end = off[d + 1];

    const int a = lane >> 3;
    const float fbv = fb[0];
    const float abr = ab[r];
    const float p2d = g_p2[d];
    const float qdv = g_qd[((size_t)r * N + d) * 4 + a];

    float acc[8];
#pragma unroll
    for (int i = 0; i < 8; i++) acc[i] = 0.f;
    float den = 0.f;

    const int* esrc = g_esrc + (size_t)r * E;
    const float* qsr = g_qs + (size_t)r * N * 4;
    const float* hwr = g_hw + (size_t)r * N * HD;

    for (int j = beg; j < end; j++) {
        int s = __ldg(esrc + j);
        float score = g_p1[s] + p2d + fbv;
        float sgn = (score > 0.f) ? 1.f : ((score < 0.f) ? -1.f : 0.f);
        float x = sgn * qsr[s * 4 + a] + qdv + abr;
        float alpha = (x > 0.f) ? x : 0.01f * x;
        float ex = expf(alpha);
        den += ex;
        float v = ex * sgn;
        const float4* hrow = reinterpret_cast<const float4*>(hwr + (size_t)s * HD) + lane * 2;
        float4 h0 = hrow[0];
        float4 h1 = hrow[1];
        acc[0] = fmaf(v, h0.x, acc[0]); acc[1] = fmaf(v, h0.y, acc[1]);
        acc[2] = fmaf(v, h0.z, acc[2]); acc[3] = fmaf(v, h0.w, acc[3]);
        acc[4] = fmaf(v, h1.x, acc[4]); acc[5] = fmaf(v, h1.y, acc[5]);
        acc[6] = fmaf(v, h1.z, acc[6]); acc[7] = fmaf(v, h1.w, acc[7]);
    }

    float sc = (den > 0.f) ? (1.f / den) : 0.f;
    float4 o0 = make_float4(acc[0] * sc, acc[1] * sc, acc[2] * sc, acc[3] * sc);
    float4 o1 = make_float4(acc[4] * sc, acc[5] * sc, acc[6] * sc, acc[7] * sc);
    float* out = g_num + (size_t)d * (RELS * HD) + r * HD + lane * 8;
    *reinterpret_cast<float4*>(out)     = o0;
    *reinterpret_cast<float4*>(out + 4) = o1;
}

// =====================================================================
// Tiled fp32 GEMM, FFMA2 + 8x8 microtile: C = A @ B + bias
// BM=128, BN=64, BK=16, 128 threads (4 warps), single-buffered smem.
// blockIdx.z batches over B/bias/C with the given strides.
// =====================================================================
#define GBM 128
#define GBN 64
#define GBK 16
__global__ __launch_bounds__(128, 4) void gemm_bias_kernel(
    const float* __restrict__ A, const float* __restrict__ B,
    const float* __restrict__ bias, float* __restrict__ C,
    int M, int N, int K,
    size_t bStride, size_t biasStride, size_t cStride)
{
    const int z = blockIdx.z;
    B    += (size_t)z * bStride;
    bias += (size_t)z * biasStride;
    C    += (size_t)z * cStride;

    __shared__ float As[GBK][GBM + 4];
    __shared__ float Bs[GBK][GBN];

    const int tid = threadIdx.x;
    const int tx  = tid & 7;          // col group: 8 cols each
    const int ty  = tid >> 3;         // row group: 0..15, 8 rows each
    const int block_m = blockIdx.y * GBM;
    const int block_n = blockIdx.x * GBN;

    ull acc2[8][4];
    const ull z2 = pack2(0.f, 0.f);
#pragma unroll
    for (int i = 0; i < 8; i++)
#pragma unroll
        for (int j = 0; j < 4; j++) acc2[i][j] = z2;

    const int b_row = tid >> 4;            // 0..7 (second half +8)
    const int b_col = (tid & 15) << 2;     // 0..60

    for (int k0 = 0; k0 < K; k0 += GBK) {
        // A tile: 128x16 = 512 float4, 4 per thread
#pragma unroll
        for (int i = 0; i < 4; i++) {
            int f   = tid + i * 128;
            int row = f >> 2;
            int kq  = (f & 3) << 2;
            int gm  = block_m + row;
            float4 av = make_float4(0.f, 0.f, 0.f, 0.f);
            if (gm < M)
                av = *reinterpret_cast<const float4*>(A + (size_t)gm * K + k0 + kq);
            As[kq + 0][row] = av.x;
            As[kq + 1][row] = av.y;
            As[kq + 2][row] = av.z;
            As[kq + 3][row] = av.w;
        }
        // B tile: 16x64 = 256 float4, 2 per thread
        {
            float4 bv0 = *reinterpret_cast<const float4*>(B + (size_t)(k0 + b_row)     * N + block_n + b_col);
            float4 bv1 = *reinterpret_cast<const float4*>(B + (size_t)(k0 + b_row + 8) * N + block_n + b_col);
            *reinterpret_cast<float4*>(&Bs[b_row][b_col])     = bv0;
            *reinterpret_cast<float4*>(&Bs[b_row + 8][b_col]) = bv1;
        }
        __syncthreads();

#pragma unroll
        for (int k = 0; k < GBK; k++) {
            float4 a0 = *reinterpret_cast<const float4*>(&As[k][ty * 8]);
            float4 a1 = *reinterpret_cast<const float4*>(&As[k][ty * 8 + 4]);
            float4 b0 = *reinterpret_cast<const float4*>(&Bs[k][tx * 8]);
            float4 b1 = *reinterpret_cast<const float4*>(&Bs[k][tx * 8 + 4]);
            ull bp[4] = {pack2(b0.x, b0.y), pack2(b0.z, b0.w),
                         pack2(b1.x, b1.y), pack2(b1.z, b1.w)};
            float ra[8] = {a0.x, a0.y, a0.z, a0.w, a1.x, a1.y, a1.z, a1.w};
#pragma unroll
            for (int i = 0; i < 8; i++) {
                ull ad = pack2(ra[i], ra[i]);
                ffma2(acc2[i][0], ad, bp[0]);
                ffma2(acc2[i][1], ad, bp[1]);
                ffma2(acc2[i][2], ad, bp[2]);
                ffma2(acc2[i][3], ad, bp[3]);
            }
        }
        __syncthreads();
    }

    const int n0 = block_n + tx * 8;
    float4 bb0 = *reinterpret_cast<const float4*>(bias + n0);
    float4 bb1 = *reinterpret_cast<const float4*>(bias + n0 + 4);
#pragma unroll
    for (int i = 0; i < 8; i++) {
        int m = block_m + ty * 8 + i;
        if (m >= M) continue;
        float4 o0, o1;
        unpack2(acc2[i][0], o0.x, o0.y);
        unpack2(acc2[i][1], o0.z, o0.w);
        unpack2(acc2[i][2], o1.x, o1.y);
        unpack2(acc2[i][3], o1.z, o1.w);
        o0.x += bb0.x; o0.y += bb0.y; o0.z += bb0.z; o0.w += bb0.w;
        o1.x += bb1.x; o1.y += bb1.y; o1.z += bb1.z; o1.w += bb1.w;
        *reinterpret_cast<float4*>(C + (size_t)m * N + n0)     = o0;
        *reinterpret_cast<float4*>(C + (size_t)m * N + n0 + 4) = o1;
    }
}

// ---------------- launch ----------------
extern "C" void kernel_launch(void* const* d_in, const int* in_sizes, int n_in,
                              void* d_out, int out_size)
{
    const float* h    = (const float*)d_in[0];
    const float* dW   = (const float*)d_in[1];
    const float* db   = (const float*)d_in[2];
    const float* fW   = (const float*)d_in[3];
    const float* fb   = (const float*)d_in[4];
    const float* wW   = (const float*)d_in[5];
    const float* wb   = (const float*)d_in[6];
    const float* aW   = (const float*)d_in[7];
    const float* ab   = (const float*)d_in[8];
    const float* linW = (const float*)d_in[9];
    const float* linb = (const float*)d_in[10];
    const int*   src  = (const int*)d_in[11];
    const int*   dst  = (const int*)d_in[12];

    const int N = in_sizes[0] / KIN;        // 50000
    const int E = in_sizes[11] / RELS;      // 300000

    float *p_hw, *p_num;
    cudaGetSymbolAddress((void**)&p_hw,  g_hw);
    cudaGetSymbolAddress((void**)&p_num, g_num);

    // folded projection vectors + constants, then per-node scalars
    prep_U_kernel<<<32, 128>>>(dW, fW, wW, aW);
    prep_Uc_kernel<<<1, 1024>>>(db, fW, wb, aW);
    node_scalars_kernel<<<(N + 7) / 8, 256>>>(h, N);

    // ---- CSR build (per relation) ----
    zero_cnt_kernel<<<(RELS * N + 255) / 256, 256>>>(RELS * N);
    {
        dim3 egrid((E + 255) / 256, RELS);
        count_kernel<<<egrid, 256>>>(dst, E, N);
        scan_kernel<<<RELS, 1024>>>(N);
        copy_cur_kernel<<<(RELS * N + 255) / 256, 256>>>(N);
        scatter_kernel<<<egrid, 256>>>(src, dst, E, N);
    }

    // hw_r = h @ wW[r] + wb[r]  — batched over blockIdx.z
    {
        dim3 ggrid(HD / GBN, (N + GBM - 1) / GBM, RELS);   // (4, 391, 3)
        gemm_bias_kernel<<<ggrid, 128>>>(
            h, wW, wb, p_hw, N, HD, KIN,
            (size_t)KIN * HD, (size_t)HD, (size_t)N * HD);
    }

    // per-destination gather: fused attention softmax + aggregation + normalize
    {
        dim3 ggrid((N + 7) / 8, RELS);
        gather_kernel<<<ggrid, 256>>>(fb, ab, E, N);
    }

    // out = num @ linW + linb
    {
        dim3 ggrid(HD / GBN, (N + GBM - 1) / GBM, 1);
        gemm_bias_kernel<<<ggrid, 128>>>(
            p_num, linW, linb, (float*)d_out, N, HD, RELS * HD, 0, 0, 0);
    }
}

// round 15
// speedup vs baseline: 1.4882x; 1.3010x over previous
#include <cuda_runtime.h>
#include <cuda_bf16.h>
#include <cstdint>

#define RELS 3
#define NMAX 50000
#define EMAX 300000
#define HD   256      // H = HF*AH
#define KIN  128      // in_feats
#define NN   256      // GEMM output width
#define BKTOT 1152    // packed B row length: 3*128 (wW) + 768 (linW)

// ---------------- scratch (static device globals; no allocation) ----------------
__device__ float g_hw  [(size_t)RELS * NMAX * HD];   // 153.6 MB
__device__ float g_num [(size_t)NMAX * RELS * HD];   // 153.6 MB (concat layout [N, 768])
__device__ float g_p1  [NMAX];
__device__ float g_p2  [NMAX];
__device__ float g_qs  [(size_t)RELS * NMAX * 4];
__device__ float g_qd  [(size_t)RELS * NMAX * 4];
__device__ float g_U   [32 * KIN];                   // folded projection vectors [col][k]
__device__ float g_Uc  [32];                         // folded constants per col
// CSR scratch
__device__ int g_cnt [RELS * NMAX];
__device__ int g_cur [RELS * NMAX];
__device__ int g_off [RELS * (NMAX + 1)];
__device__ int g_esrc[(size_t)RELS * EMAX];
// packed B: n-major [NN][BKTOT], bf16 hi and lo planes
__device__ __align__(16) __nv_bfloat16 g_Bh[(size_t)NN * BKTOT];
__device__ __align__(16) __nv_bfloat16 g_Bl[(size_t)NN * BKTOT];

// ---------------- helpers ----------------
__device__ __forceinline__ void mma_bf16(float* c, uint32_t a0, uint32_t a1,
                                         uint32_t a2, uint32_t a3,
                                         uint32_t b0, uint32_t b1) {
    asm volatile("mma.sync.aligned.m16n8k16.row.col.f32.bf16.bf16.f32 "
                 "{%0,%1,%2,%3}, {%4,%5,%6,%7}, {%8,%9}, {%0,%1,%2,%3};"
                 : "+f"(c[0]), "+f"(c[1]), "+f"(c[2]), "+f"(c[3])
                 : "r"(a0), "r"(a1), "r"(a2), "r"(a3), "r"(b0), "r"(b1));
}

// =====================================================================
// Pack B (wW / linW) once into bf16 hi/lo planes, n-major [256][1152]:
//   cols [0,384)   : wW, col = r*128 + k  ->  wW[r][k][n]
//   cols [384,1152): linW, col = 384 + k  ->  linW[k][n]
// =====================================================================
__global__ void pack_B_kernel(const float* __restrict__ wW, const float* __restrict__ linW)
{
    int idx = blockIdx.x * blockDim.x + threadIdx.x;
    if (idx >= NN * BKTOT) return;
    int n = idx / BKTOT;
    int c = idx - n * BKTOT;
    float v;
    if (c < 384) v = wW[(size_t)c * NN + n];             // (r*128+k)*256 + n
    else         v = linW[(size_t)(c - 384) * NN + n];
    __nv_bfloat16 hi = __float2bfloat16(v);
    float lo = v - __bfloat162float(hi);
    g_Bh[(size_t)n * BKTOT + c] = hi;
    g_Bl[(size_t)n * BKTOT + c] = __float2bfloat16(lo);
}

// =====================================================================
// HMMA GEMM (mma.sync m16n8k16 bf16, split hi/lo): C = A @ B + bias
// BM=128, BN=64, BK=32, 256 threads, warp grid 4(m) x 2(n),
// each warp 32x32 = 2 m-tiles x 4 n-tiles, 3 split products per tile.
// A fp32 converted to bf16 hi/lo during the smem stage.
// z batches relations: B k-window = kb0 + z*kzStride.
// =====================================================================
#define BM 128
#define BN 64
#define BK 32
#define APAD 40   // bf16 stride (20 b32) — conflict-free fragment loads

__global__ __launch_bounds__(256) void mma_gemm_kernel(
    const float* __restrict__ A, const float* __restrict__ bias,
    float* __restrict__ C, int M, int K, int kb0, int kzStride,
    size_t biasStride, size_t cStride)
{
    __shared__ __nv_bfloat16 As_h[BM][APAD], As_l[BM][APAD];
    __shared__ __nv_bfloat16 Bs_h[BN][APAD], Bs_l[BN][APAD];

    const int tid  = threadIdx.x;
    const int lane = tid & 31, wid = tid >> 5;
    const int bm = blockIdx.y * BM;
    const int bn = blockIdx.x * BN;
    const int z  = blockIdx.z;
    const int kbase = kb0 + z * kzStride;

    bias += (size_t)z * biasStride;
    C    += (size_t)z * cStride;

    const int wm  = (wid >> 1) * 32;   // warp m offset within tile
    const int wn  = (wid & 1) * 32;    // warp n offset within tile
    const int grp = lane >> 2;         // 0..7
    const int tig = lane & 3;          // 0..3

    float acc[2][4][4];
#pragma unroll
    for (int mt = 0; mt < 2; mt++)
#pragma unroll
        for (int nt = 0; nt < 4; nt++)
#pragma unroll
            for (int q = 0; q < 4; q++) acc[mt][nt][q] = 0.f;

    for (int k0 = 0; k0 < K; k0 += BK) {
        // ---- stage A: 128x32 fp32 -> bf16 hi/lo ----
#pragma unroll
        for (int i = 0; i < 4; i++) {
            int idx = tid + i * 256;         // float4 index, 0..1023
            int row = idx >> 3;              // 8 float4 per 32-wide row
            int kq  = (idx & 7) << 2;
            int gm  = bm + row;
            float4 v = make_float4(0.f, 0.f, 0.f, 0.f);
            if (gm < M) v = *reinterpret_cast<const float4*>(A + (size_t)gm * K + k0 + kq);
            float vv[4] = {v.x, v.y, v.z, v.w};
#pragma unroll
            for (int j = 0; j < 4; j++) {
                __nv_bfloat16 hi = __float2bfloat16(vv[j]);
                As_h[row][kq + j] = hi;
                As_l[row][kq + j] = __float2bfloat16(vv[j] - __bfloat162float(hi));
            }
        }
        // ---- stage B: 64x32 bf16 hi/lo copy from packed gmem ----
#pragma unroll
        for (int i = 0; i < 2; i++) {
            int idx = tid + i * 256;         // u64 index, 0..511 (4 bf16 each)
            int n  = idx >> 3;
            int kq = (idx & 7) << 2;
            size_t src = (size_t)(bn + n) * BKTOT + kbase + k0 + kq;
            *reinterpret_cast<uint64_t*>(&Bs_h[n][kq]) =
                *reinterpret_cast<const uint64_t*>(g_Bh + src);
            *reinterpret_cast<uint64_t*>(&Bs_l[n][kq]) =
                *reinterpret_cast<const uint64_t*>(g_Bl + src);
        }
        __syncthreads();

        // ---- compute: 2 k-steps of 16 ----
#pragma unroll
        for (int ks = 0; ks < 2; ks++) {
            const int kb32 = ks * 8;         // b32 col offset (16 bf16)
            uint32_t ah[2][4], al[2][4];
#pragma unroll
            for (int mt = 0; mt < 2; mt++) {
                int r0 = wm + mt * 16 + grp;
                const uint32_t* p0 = reinterpret_cast<const uint32_t*>(&As_h[r0][0]);
                const uint32_t* p1 = reinterpret_cast<const uint32_t*>(&As_h[r0 + 8][0]);
                const uint32_t* q0 = reinterpret_cast<const uint32_t*>(&As_l[r0][0]);
                const uint32_t* q1 = reinterpret_cast<const uint32_t*>(&As_l[r0 + 8][0]);
                ah[mt][0] = p0[kb32 + tig];     ah[mt][1] = p1[kb32 + tig];
                ah[mt][2] = p0[kb32 + tig + 4]; ah[mt][3] = p1[kb32 + tig + 4];
                al[mt][0] = q0[kb32 + tig];     al[mt][1] = q1[kb32 + tig];
                al[mt][2] = q0[kb32 + tig + 4]; al[mt][3] = q1[kb32 + tig + 4];
            }
            uint32_t bh[4][2], bl[4][2];
#pragma unroll
            for (int nt = 0; nt < 4; nt++) {
                int n = wn + nt * 8 + grp;
                const uint32_t* p = reinterpret_cast<const uint32_t*>(&Bs_h[n][0]);
                const uint32_t* q = reinterpret_cast<const uint32_t*>(&Bs_l[n][0]);
                bh[nt][0] = p[kb32 + tig]; bh[nt][1] = p[kb32 + tig + 4];
                bl[nt][0] = q[kb32 + tig]; bl[nt][1] = q[kb32 + tig + 4];
            }
#pragma unroll
            for (int mt = 0; mt < 2; mt++)
#pragma unroll
                for (int nt = 0; nt < 4; nt++) {
                    mma_bf16(acc[mt][nt], ah[mt][0], ah[mt][1], ah[mt][2], ah[mt][3],
                             bh[nt][0], bh[nt][1]);
                    mma_bf16(acc[mt][nt], ah[mt][0], ah[mt][1], ah[mt][2], ah[mt][3],
                             bl[nt][0], bl[nt][1]);
                    mma_bf16(acc[mt][nt], al[mt][0], al[mt][1], al[mt][2], al[mt][3],
                             bh[nt][0], bh[nt][1]);
                }
        }
        __syncthreads();
    }

    // ---- epilogue ----
#pragma unroll
    for (int mt = 0; mt < 2; mt++) {
        int row0 = bm + wm + mt * 16 + grp;
#pragma unroll
        for (int nt = 0; nt < 4; nt++) {
            int col = bn + wn + nt * 8 + tig * 2;
            float2 bb = *reinterpret_cast<const float2*>(bias + col);
            if (row0 < M) {
                float2 o = make_float2(acc[mt][nt][0] + bb.x, acc[mt][nt][1] + bb.y);
                *reinterpret_cast<float2*>(C + (size_t)row0 * NN + col) = o;
            }
            if (row0 + 8 < M) {
                float2 o = make_float2(acc[mt][nt][2] + bb.x, acc[mt][nt][3] + bb.y);
                *reinterpret_cast<float2*>(C + (size_t)(row0 + 8) * NN + col) = o;
            }
        }
    }
}

// =====================================================================
// Fold all per-node scalar projections into U[32][128] (unchanged, passing)
// =====================================================================
__global__ void prep_U_kernel(const float* __restrict__ dW, const float* __restrict__ fW,
                              const float* __restrict__ wW, const float* __restrict__ aW)
{
    int col = blockIdx.x;     // 0..31
    int k   = threadIdx.x;    // 0..127
    float s = 0.f;
    if (col < 2) {
        const float* dwr = dW + (size_t)k * HD;
        for (int j = 0; j < HD; j++) {
            float f = (col == 0) ? (fW[j] + fW[512 + j]) : (fW[256 + j] - fW[512 + j]);
            s += dwr[j] * f;
        }
    } else if (col < 26) {
        int c = col - 2;
        int half = 0;
        if (c >= 12) { c -= 12; half = 1; }
        int r = c >> 2, a = c & 3;
        const float* wwr = wW + ((size_t)r * KIN + k) * HD + a * 64;
        const float* awr = aW + r * 128 + half * 64;
        for (int j = 0; j < 64; j++) s += wwr[j] * awr[j];
    }
    g_U[col * KIN + k] = s;
}

__global__ void prep_Uc_kernel(const float* __restrict__ db, const float* __restrict__ fW,
                               const float* __restrict__ wb, const float* __restrict__ aW)
{
    int col  = threadIdx.x >> 5;
    int lane = threadIdx.x & 31;
    float s = 0.f;
    if (col < 2) {
        for (int j = lane; j < HD; j += 32) {
            float f = (col == 0) ? (fW[j] + fW[512 + j]) : (fW[256 + j] - fW[512 + j]);
            s += db[j] * f;
        }
    } else if (col < 26) {
        int c = col - 2;
        int half = 0;
        if (c >= 12) { c -= 12; half = 1; }
        int r = c >> 2, a = c & 3;
        for (int j = lane; j < 64; j += 32)
            s += wb[r * HD + a * 64 + j] * aW[r * 128 + half * 64 + j];
    }
#pragma unroll
    for (int o = 16; o > 0; o >>= 1) s += __shfl_xor_sync(0xFFFFFFFFu, s, o);
    if (lane == 0) g_Uc[col] = s;
}

__global__ __launch_bounds__(256) void node_scalars_kernel(const float* __restrict__ h, int N)
{
    __shared__ float sh[8][KIN];
    const int tid  = threadIdx.x;
    const int node0 = blockIdx.x * 8;
    {
        int row = tid >> 5;
        int w4  = tid & 31;
        int n = node0 + row;
        float4 v = make_float4(0.f, 0.f, 0.f, 0.f);
        if (n < N) v = *reinterpret_cast<const float4*>(h + (size_t)n * KIN + w4 * 4);
        *reinterpret_cast<float4*>(&sh[row][w4 * 4]) = v;
    }
    __syncthreads();

    const int w    = tid >> 5;
    const int lane = tid & 31;
    const int n    = node0 + w;
    if (n >= N || lane >= 26) return;

    const float4* urow = reinterpret_cast<const float4*>(g_U + lane * KIN);
    const float4* hrow = reinterpret_cast<const float4*>(&sh[w][0]);
    float acc = 0.f;
#pragma unroll
    for (int q = 0; q < 32; q++) {
        float4 hv = hrow[q];
        float4 uv = urow[q];
        acc += hv.x * uv.x + hv.y * uv.y + hv.z * uv.z + hv.w * uv.w;
    }
    acc += g_Uc[lane];

    if (lane == 0)      g_p1[n] = acc;
    else if (lane == 1) g_p2[n] = acc;
    else if (lane < 14) {
        int c = lane - 2, r = c >> 2, a = c & 3;
        g_qs[((size_t)r * N + n) * 4 + a] = acc;
    } else {
        int c = lane - 14, r = c >> 2, a = c & 3;
        g_qd[((size_t)r * N + n) * 4 + a] = acc;
    }
}

// ---------------- CSR build (unchanged, passing) ----------------
__global__ void zero_cnt_kernel(int n) {
    int i = blockIdx.x * blockDim.x + threadIdx.x;
    if (i < n) g_cnt[i] = 0;
}
__global__ void count_kernel(const int* __restrict__ dst, int E, int N) {
    int r = blockIdx.y;
    int e = blockIdx.x * blockDim.x + threadIdx.x;
    if (e >= E) return;
    int d = __ldg(dst + (size_t)r * E + e);
    atomicAdd(g_cnt + r * N + d, 1);
}
__global__ __launch_bounds__(1024) void scan_kernel(int N) {
    const int r    = blockIdx.x;
    const int tid  = threadIdx.x;
    const int lane = tid & 31, wid = tid >> 5;
    __shared__ int wsum[32];
    __shared__ int carry;
    if (tid == 0) carry = 0;
    __syncthreads();
    const int* cnt = g_cnt + r * N;
    int* off = g_off + r * (N + 1);
    for (int base = 0; base < N; base += 1024) {
        int i = base + tid;
        int v = (i < N) ? cnt[i] : 0;
        int x = v;
#pragma unroll
        for (int o = 1; o < 32; o <<= 1) {
            int y = __shfl_up_sync(0xFFFFFFFFu, x, o);
            if (lane >= o) x += y;
        }
        if (lane == 31) wsum[wid] = x;
        __syncthreads();
        if (wid == 0) {
            int y = wsum[lane];
#pragma unroll
            for (int o = 1; o < 32; o <<= 1) {
                int z = __shfl_up_sync(0xFFFFFFFFu, y, o);
                if (lane >= o) y += z;
            }
            wsum[lane] = y;
        }
        __syncthreads();
        int prefix = (wid > 0) ? wsum[wid - 1] : 0;
        int c = carry;
        if (i < N) off[i] = c + prefix + x - v;
        int total = wsum[31];
        __syncthreads();
        if (tid == 0) carry = c + total;
        __syncthreads();
    }
    if (tid == 0) off[N] = carry;
}
__global__ void copy_cur_kernel(int N) {
    int i = blockIdx.x * blockDim.x + threadIdx.x;
    if (i >= RELS * N) return;
    int r = i / N, n = i - r * N;
    g_cur[i] = g_off[r * (N + 1) + n];
}
__global__ void scatter_kernel(const int* __restrict__ src, const int* __restrict__ dst,
                               int E, int N) {
    int r = blockIdx.y;
    int e = blockIdx.x * blockDim.x + threadIdx.x;
    if (e >= E) return;
    int d = __ldg(dst + (size_t)r * E + e);
    int pos = atomicAdd(g_cur + r * N + d, 1);
    g_esrc[(size_t)r * E + pos] = __ldg(src + (size_t)r * E + e);
}

// ---------------- gather (unchanged, passing) ----------------
__global__ __launch_bounds__(256) void gather_kernel(
    const float* __restrict__ fb, const float* __restrict__ ab, int E, int N)
{
    const int r    = blockIdx.y;
    const int d    = blockIdx.x * 8 + (threadIdx.x >> 5);
    const int lane = threadIdx.x & 31;
    if (d >= N) return;

    const int* off = g_off + r * (N + 1);
    const int beg = off[d], end = off[d + 1];

    const int a = lane >> 3;
    const float fbv = fb[0];
    const float abr = ab[r];
    const float p2d = g_p2[d];
    const float qdv = g_qd[((size_t)r * N + d) * 4 + a];

    float acc[8];
#pragma unroll
    for (int i = 0; i < 8; i++) acc[i] = 0.f;
    float den = 0.f;

    const int* esrc = g_esrc + (size_t)r * E;
    const float* qsr = g_qs + (size_t)r * N * 4;
    const float* hwr = g_hw + (size_t)r * N * HD;

    for (int j = beg; j < end; j++) {
        int s = __ldg(esrc + j);
        float score = g_p1[s] + p2d + fbv;
        float sgn = (score > 0.f) ? 1.f : ((score < 0.f) ? -1.f : 0.f);
        float x = sgn * qsr[s * 4 + a] + qdv + abr;
        float alpha = (x > 0.f) ? x : 0.01f * x;
        float ex = expf(alpha);
        den += ex;
        float v = ex * sgn;
        const float4* hrow = reinterpret_cast<const float4*>(hwr + (size_t)s * HD) + lane * 2;
        float4 h0 = hrow[0];
        float4 h1 = hrow[1];
        acc[0] = fmaf(v, h0.x, acc[0]); acc[1] = fmaf(v, h0.y, acc[1]);
        acc[2] = fmaf(v, h0.z, acc[2]); acc[3] = fmaf(v, h0.w, acc[3]);
        acc[4] = fmaf(v, h1.x, acc[4]); acc[5] = fmaf(v, h1.y, acc[5]);
        acc[6] = fmaf(v, h1.z, acc[6]); acc[7] = fmaf(v, h1.w, acc[7]);
    }

    float sc = (den > 0.f) ? (1.f / den) : 0.f;
    float4 o0 = make_float4(acc[0] * sc, acc[1] * sc, acc[2] * sc, acc[3] * sc);
    float4 o1 = make_float4(acc[4] * sc, acc[5] * sc, acc[6] * sc, acc[7] * sc);
    float* out = g_num + (size_t)d * (RELS * HD) + r * HD + lane * 8;
    *reinterpret_cast<float4*>(out)     = o0;
    *reinterpret_cast<float4*>(out + 4) = o1;
}

// ---------------- launch ----------------
extern "C" void kernel_launch(void* const* d_in, const int* in_sizes, int n_in,
                              void* d_out, int out_size)
{
    const float* h    = (const float*)d_in[0];
    const float* dW   = (const float*)d_in[1];
    const float* db   = (const float*)d_in[2];
    const float* fW   = (const float*)d_in[3];
    const float* fb   = (const float*)d_in[4];
    const float* wW   = (const float*)d_in[5];
    const float* wb   = (const float*)d_in[6];
    const float* aW   = (const float*)d_in[7];
    const float* ab   = (const float*)d_in[8];
    const float* linW = (const float*)d_in[9];
    const float* linb = (const float*)d_in[10];
    const int*   src  = (const int*)d_in[11];
    const int*   dst  = (const int*)d_in[12];

    const int N = in_sizes[0] / KIN;        // 50000
    const int E = in_sizes[11] / RELS;      // 300000
    const int tiles = (N + BM - 1) / BM;    // 391

    float *p_hw, *p_num;
    cudaGetSymbolAddress((void**)&p_hw,  g_hw);
    cudaGetSymbolAddress((void**)&p_num, g_num);

    // prep: folded projections, packed B planes, per-node scalars
    prep_U_kernel<<<32, 128>>>(dW, fW, wW, aW);
    prep_Uc_kernel<<<1, 1024>>>(db, fW, wb, aW);
    pack_B_kernel<<<(NN * BKTOT + 255) / 256, 256>>>(wW, linW);
    node_scalars_kernel<<<(N + 7) / 8, 256>>>(h, N);

    // CSR build
    zero_cnt_kernel<<<(RELS * N + 255) / 256, 256>>>(RELS * N);
    {
        dim3 egrid((E + 255) / 256, RELS);
        count_kernel<<<egrid, 256>>>(dst, E, N);
        scan_kernel<<<RELS, 1024>>>(N);
        copy_cur_kernel<<<(RELS * N + 255) / 256, 256>>>(N);
        scatter_kernel<<<egrid, 256>>>(src, dst, E, N);
    }

    // hw_r = h @ wW[r] + wb[r]  — HMMA split-bf16, z = relation (k-window r*128)
    {
        dim3 ggrid(NN / BN, tiles, RELS);   // (4, 391, 3)
        mma_gemm_kernel<<<ggrid, 256>>>(
            h, wb, p_hw, N, KIN, /*kb0=*/0, /*kzStride=*/KIN,
            /*biasStride=*/HD, /*cStride=*/(size_t)N * HD);
    }

    // per-destination gather (fused softmax + aggregate + normalize)
    {
        dim3 ggrid((N + 7) / 8, RELS);
        gather_kernel<<<ggrid, 256>>>(fb, ab, E, N);
    }

    // out = num @ linW + linb  — HMMA split-bf16, K=768 (k-window base 384)
    {
        dim3 ggrid(NN / BN, tiles, 1);
        mma_gemm_kernel<<<ggrid, 256>>>(
            p_num, linb, (float*)d_out, N, RELS * HD, /*kb0=*/384, /*kzStride=*/0,
            /*biasStride=*/0, /*cStride=*/0);
    }
}

// round 16
// speedup vs baseline: 1.7177x; 1.1542x over previous
#include <cuda_runtime.h>
#include <cuda_bf16.h>
#include <cstdint>

#define RELS 3
#define NMAX 50000
#define EMAX 300000
#define HD   256      // H = HF*AH
#define KIN  128      // in_feats
#define NN   256      // GEMM output width
#define BKTOT 1152    // packed B row length: 3*128 (wW) + 768 (linW)

// ---------------- scratch (static device globals; no allocation) ----------------
__device__ float g_hw  [(size_t)RELS * NMAX * HD];   // 153.6 MB
__device__ float g_num [(size_t)NMAX * RELS * HD];   // 153.6 MB (concat layout [N, 768])
__device__ float g_p1  [NMAX];
__device__ float g_p2  [NMAX];
__device__ float g_qs  [(size_t)RELS * NMAX * 4];
__device__ float g_qd  [(size_t)RELS * NMAX * 4];
__device__ float g_U   [32 * KIN];                   // folded projection vectors [col][k]
__device__ float g_Uc  [32];                         // folded constants per col
// CSR scratch
__device__ int g_cnt [RELS * NMAX];
__device__ int g_cur [RELS * NMAX];
__device__ int g_off [RELS * (NMAX + 1)];
__device__ int g_esrc[(size_t)RELS * EMAX];
// packed B: n-major [NN][BKTOT], bf16 hi and lo planes
__device__ __align__(16) __nv_bfloat16 g_Bh[(size_t)NN * BKTOT];
__device__ __align__(16) __nv_bfloat16 g_Bl[(size_t)NN * BKTOT];

// ---------------- helpers ----------------
__device__ __forceinline__ void mma_bf16(float* c, uint32_t a0, uint32_t a1,
                                         uint32_t a2, uint32_t a3,
                                         uint32_t b0, uint32_t b1) {
    asm volatile("mma.sync.aligned.m16n8k16.row.col.f32.bf16.bf16.f32 "
                 "{%0,%1,%2,%3}, {%4,%5,%6,%7}, {%8,%9}, {%0,%1,%2,%3};"
                 : "+f"(c[0]), "+f"(c[1]), "+f"(c[2]), "+f"(c[3])
                 : "r"(a0), "r"(a1), "r"(a2), "r"(a3), "r"(b0), "r"(b1));
}

// =====================================================================
// Pack B (wW / linW) once into bf16 hi/lo planes, n-major [256][1152]
// =====================================================================
__global__ void pack_B_kernel(const float* __restrict__ wW, const float* __restrict__ linW)
{
    int idx = blockIdx.x * blockDim.x + threadIdx.x;
    if (idx >= NN * BKTOT) return;
    int n = idx / BKTOT;
    int c = idx - n * BKTOT;
    float v;
    if (c < 384) v = wW[(size_t)c * NN + n];             // (r*128+k)*256 + n
    else         v = linW[(size_t)(c - 384) * NN + n];
    __nv_bfloat16 hi = __float2bfloat16(v);
    float lo = v - __bfloat162float(hi);
    g_Bh[(size_t)n * BKTOT + c] = hi;
    g_Bl[(size_t)n * BKTOT + c] = __float2bfloat16(lo);
}

// =====================================================================
// HMMA GEMM (mma.sync m16n8k16 bf16, split hi/lo): C = A @ B + bias
// (unchanged from R15 — passing, tensor-pipe bound)
// =====================================================================
#define BM 128
#define BN 64
#define BK 32
#define APAD 40

__global__ __launch_bounds__(256) void mma_gemm_kernel(
    const float* __restrict__ A, const float* __restrict__ bias,
    float* __restrict__ C, int M, int K, int kb0, int kzStride,
    size_t biasStride, size_t cStride)
{
    __shared__ __nv_bfloat16 As_h[BM][APAD], As_l[BM][APAD];
    __shared__ __nv_bfloat16 Bs_h[BN][APAD], Bs_l[BN][APAD];

    const int tid  = threadIdx.x;
    const int lane = tid & 31, wid = tid >> 5;
    const int bm = blockIdx.y * BM;
    const int bn = blockIdx.x * BN;
    const int z  = blockIdx.z;
    const int kbase = kb0 + z * kzStride;

    bias += (size_t)z * biasStride;
    C    += (size_t)z * cStride;

    const int wm  = (wid >> 1) * 32;
    const int wn  = (wid & 1) * 32;
    const int grp = lane >> 2;
    const int tig = lane & 3;

    float acc[2][4][4];
#pragma unroll
    for (int mt = 0; mt < 2; mt++)
#pragma unroll
        for (int nt = 0; nt < 4; nt++)
#pragma unroll
            for (int q = 0; q < 4; q++) acc[mt][nt][q] = 0.f;

    for (int k0 = 0; k0 < K; k0 += BK) {
#pragma unroll
        for (int i = 0; i < 4; i++) {
            int idx = tid + i * 256;
            int row = idx >> 3;
            int kq  = (idx & 7) << 2;
            int gm  = bm + row;
            float4 v = make_float4(0.f, 0.f, 0.f, 0.f);
            if (gm < M) v = *reinterpret_cast<const float4*>(A + (size_t)gm * K + k0 + kq);
            float vv[4] = {v.x, v.y, v.z, v.w};
#pragma unroll
            for (int j = 0; j < 4; j++) {
                __nv_bfloat16 hi = __float2bfloat16(vv[j]);
                As_h[row][kq + j] = hi;
                As_l[row][kq + j] = __float2bfloat16(vv[j] - __bfloat162float(hi));
            }
        }
#pragma unroll
        for (int i = 0; i < 2; i++) {
            int idx = tid + i * 256;
            int n  = idx >> 3;
            int kq = (idx & 7) << 2;
            size_t src = (size_t)(bn + n) * BKTOT + kbase + k0 + kq;
            *reinterpret_cast<uint64_t*>(&Bs_h[n][kq]) =
                *reinterpret_cast<const uint64_t*>(g_Bh + src);
            *reinterpret_cast<uint64_t*>(&Bs_l[n][kq]) =
                *reinterpret_cast<const uint64_t*>(g_Bl + src);
        }
        __syncthreads();

#pragma unroll
        for (int ks = 0; ks < 2; ks++) {
            const int kb32 = ks * 8;
            uint32_t ah[2][4], al[2][4];
#pragma unroll
            for (int mt = 0; mt < 2; mt++) {
                int r0 = wm + mt * 16 + grp;
                const uint32_t* p0 = reinterpret_cast<const uint32_t*>(&As_h[r0][0]);
                const uint32_t* p1 = reinterpret_cast<const uint32_t*>(&As_h[r0 + 8][0]);
                const uint32_t* q0 = reinterpret_cast<const uint32_t*>(&As_l[r0][0]);
                const uint32_t* q1 = reinterpret_cast<const uint32_t*>(&As_l[r0 + 8][0]);
                ah[mt][0] = p0[kb32 + tig];     ah[mt][1] = p1[kb32 + tig];
                ah[mt][2] = p0[kb32 + tig + 4]; ah[mt][3] = p1[kb32 + tig + 4];
                al[mt][0] = q0[kb32 + tig];     al[mt][1] = q1[kb32 + tig];
                al[mt][2] = q0[kb32 + tig + 4]; al[mt][3] = q1[kb32 + tig + 4];
            }
            uint32_t bh[4][2], bl[4][2];
#pragma unroll
            for (int nt = 0; nt < 4; nt++) {
                int n = wn + nt * 8 + grp;
                const uint32_t* p = reinterpret_cast<const uint32_t*>(&Bs_h[n][0]);
                const uint32_t* q = reinterpret_cast<const uint32_t*>(&Bs_l[n][0]);
                bh[nt][0] = p[kb32 + tig]; bh[nt][1] = p[kb32 + tig + 4];
                bl[nt][0] = q[kb32 + tig]; bl[nt][1] = q[kb32 + tig + 4];
            }
#pragma unroll
            for (int mt = 0; mt < 2; mt++)
#pragma unroll
                for (int nt = 0; nt < 4; nt++) {
                    mma_bf16(acc[mt][nt], ah[mt][0], ah[mt][1], ah[mt][2], ah[mt][3],
                             bh[nt][0], bh[nt][1]);
                    mma_bf16(acc[mt][nt], ah[mt][0], ah[mt][1], ah[mt][2], ah[mt][3],
                             bl[nt][0], bl[nt][1]);
                    mma_bf16(acc[mt][nt], al[mt][0], al[mt][1], al[mt][2], al[mt][3],
                             bh[nt][0], bh[nt][1]);
                }
        }
        __syncthreads();
    }

#pragma unroll
    for (int mt = 0; mt < 2; mt++) {
        int row0 = bm + wm + mt * 16 + grp;
#pragma unroll
        for (int nt = 0; nt < 4; nt++) {
            int col = bn + wn + nt * 8 + tig * 2;
            float2 bb = *reinterpret_cast<const float2*>(bias + col);
            if (row0 < M) {
                float2 o = make_float2(acc[mt][nt][0] + bb.x, acc[mt][nt][1] + bb.y);
                *reinterpret_cast<float2*>(C + (size_t)row0 * NN + col) = o;
            }
            if (row0 + 8 < M) {
                float2 o = make_float2(acc[mt][nt][2] + bb.x, acc[mt][nt][3] + bb.y);
                *reinterpret_cast<float2*>(C + (size_t)(row0 + 8) * NN + col) = o;
            }
        }
    }
}

// =====================================================================
// prep kernels (unchanged, passing)
// =====================================================================
__global__ void prep_U_kernel(const float* __restrict__ dW, const float* __restrict__ fW,
                              const float* __restrict__ wW, const float* __restrict__ aW)
{
    int col = blockIdx.x;     // 0..31
    int k   = threadIdx.x;    // 0..127
    float s = 0.f;
    if (col < 2) {
        const float* dwr = dW + (size_t)k * HD;
        for (int j = 0; j < HD; j++) {
            float f = (col == 0) ? (fW[j] + fW[512 + j]) : (fW[256 + j] - fW[512 + j]);
            s += dwr[j] * f;
        }
    } else if (col < 26) {
        int c = col - 2;
        int half = 0;
        if (c >= 12) { c -= 12; half = 1; }
        int r = c >> 2, a = c & 3;
        const float* wwr = wW + ((size_t)r * KIN + k) * HD + a * 64;
        const float* awr = aW + r * 128 + half * 64;
        for (int j = 0; j < 64; j++) s += wwr[j] * awr[j];
    }
    g_U[col * KIN + k] = s;
}

__global__ void prep_Uc_kernel(const float* __restrict__ db, const float* __restrict__ fW,
                               const float* __restrict__ wb, const float* __restrict__ aW)
{
    int col  = threadIdx.x >> 5;
    int lane = threadIdx.x & 31;
    float s = 0.f;
    if (col < 2) {
        for (int j = lane; j < HD; j += 32) {
            float f = (col == 0) ? (fW[j] + fW[512 + j]) : (fW[256 + j] - fW[512 + j]);
            s += db[j] * f;
        }
    } else if (col < 26) {
        int c = col - 2;
        int half = 0;
        if (c >= 12) { c -= 12; half = 1; }
        int r = c >> 2, a = c & 3;
        for (int j = lane; j < 64; j += 32)
            s += wb[r * HD + a * 64 + j] * aW[r * 128 + half * 64 + j];
    }
#pragma unroll
    for (int o = 16; o > 0; o >>= 1) s += __shfl_xor_sync(0xFFFFFFFFu, s, o);
    if (lane == 0) g_Uc[col] = s;
}

// =====================================================================
// Node scalars — smem-tiled mini-GEMM: scal[N,32] = h[N,128] @ U^T.
// Block = 64 nodes. U staged transposed (su[k][col], bank=col, conflict-
// free); h staged once, read as float4 broadcasts. Thread = (col=lane,
// 8 nodes). Replaces the L1-bound per-node U re-read (153.8 us -> ~10 us).
// =====================================================================
__global__ __launch_bounds__(256) void node_scalars_kernel(const float* __restrict__ h, int N)
{
    __shared__ float sh[64][KIN];     // 32 KB
    __shared__ float su[KIN][32];     // 16 KB, su[k][col]
    const int tid   = threadIdx.x;
    const int node0 = blockIdx.x * 64;

    // stage U transposed (coalesced gmem read; one-time scattered STS)
    for (int i = tid; i < 32 * KIN; i += 256) {
        int col = i >> 7, k = i & 127;
        su[k][col] = g_U[i];
    }
    // stage 64 h rows (float4, coalesced, conflict-free STS.128)
    for (int i = tid; i < 64 * 32; i += 256) {
        int row = i >> 5, c4 = i & 31;
        int n = node0 + row;
        float4 v = make_float4(0.f, 0.f, 0.f, 0.f);
        if (n < N) v = *reinterpret_cast<const float4*>(h + (size_t)n * KIN + c4 * 4);
        *reinterpret_cast<float4*>(&sh[row][c4 * 4]) = v;
    }
    __syncthreads();

    const int tx = tid & 31;     // column
    const int ty = tid >> 5;     // node octet
    float acc[8];
#pragma unroll
    for (int i = 0; i < 8; i++) acc[i] = 0.f;

    for (int k4 = 0; k4 < 32; k4++) {
        float u0 = su[k4 * 4 + 0][tx];
        float u1 = su[k4 * 4 + 1][tx];
        float u2 = su[k4 * 4 + 2][tx];
        float u3 = su[k4 * 4 + 3][tx];
#pragma unroll
        for (int i = 0; i < 8; i++) {
            float4 hv = *reinterpret_cast<const float4*>(&sh[ty * 8 + i][k4 * 4]);
            acc[i] += hv.x * u0 + hv.y * u1 + hv.z * u2 + hv.w * u3;
        }
    }

    if (tx < 26) {
        float uc = g_Uc[tx];
#pragma unroll
        for (int i = 0; i < 8; i++) {
            int n = node0 + ty * 8 + i;
            if (n >= N) break;
            float val = acc[i] + uc;
            if (tx == 0)      g_p1[n] = val;
            else if (tx == 1) g_p2[n] = val;
            else if (tx < 14) {
                int c = tx - 2, r = c >> 2, a = c & 3;
                g_qs[((size_t)r * N + n) * 4 + a] = val;
            } else {
                int c = tx - 14, r = c >> 2, a = c & 3;
                g_qd[((size_t)r * N + n) * 4 + a] = val;
            }
        }
    }
}

// ---------------- CSR build ----------------
__global__ void zero_cnt_kernel(int n) {
    int i = blockIdx.x * blockDim.x + threadIdx.x;
    if (i < n) g_cnt[i] = 0;
}
__global__ void count_kernel(const int* __restrict__ dst, int E, int N) {
    int r = blockIdx.y;
    int e = blockIdx.x * blockDim.x + threadIdx.x;
    if (e >= E) return;
    int d = __ldg(dst + (size_t)r * E + e);
    atomicAdd(g_cnt + r * N + d, 1);
}
// exclusive scan; also seeds g_cur (copy_cur folded in)
__global__ __launch_bounds__(1024) void scan_kernel(int N) {
    const int r    = blockIdx.x;
    const int tid  = threadIdx.x;
    const int lane = tid & 31, wid = tid >> 5;
    __shared__ int wsum[32];
    __shared__ int carry;
    if (tid == 0) carry = 0;
    __syncthreads();
    const int* cnt = g_cnt + r * N;
    int* off = g_off + r * (N + 1);
    int* cur = g_cur + r * N;
    for (int base = 0; base < N; base += 1024) {
        int i = base + tid;
        int v = (i < N) ? cnt[i] : 0;
        int x = v;
#pragma unroll
        for (int o = 1; o < 32; o <<= 1) {
            int y = __shfl_up_sync(0xFFFFFFFFu, x, o);
            if (lane >= o) x += y;
        }
        if (lane == 31) wsum[wid] = x;
        __syncthreads();
        if (wid == 0) {
            int y = wsum[lane];
#pragma unroll
            for (int o = 1; o < 32; o <<= 1) {
                int z = __shfl_up_sync(0xFFFFFFFFu, y, o);
                if (lane >= o) y += z;
            }
            wsum[lane] = y;
        }
        __syncthreads();
        int prefix = (wid > 0) ? wsum[wid - 1] : 0;
        int c = carry;
        if (i < N) {
            int val = c + prefix + x - v;
            off[i] = val;
            cur[i] = val;
        }
        int total = wsum[31];
        __syncthreads();
        if (tid == 0) carry = c + total;
        __syncthreads();
    }
    if (tid == 0) off[N] = carry;
}
__global__ void scatter_kernel(const int* __restrict__ src, const int* __restrict__ dst,
                               int E, int N) {
    int r = blockIdx.y;
    int e = blockIdx.x * blockDim.x + threadIdx.x;
    if (e >= E) return;
    int d = __ldg(dst + (size_t)r * E + e);
    int pos = atomicAdd(g_cur + r * N + d, 1);
    g_esrc[(size_t)r * E + pos] = __ldg(src + (size_t)r * E + e);
}

// ---------------- gather (unchanged, passing) ----------------
__global__ __launch_bounds__(256) void gather_kernel(
    const float* __restrict__ fb, const float* __restrict__ ab, int E, int N)
{
    const int r    = blockIdx.y;
    const int d    = blockIdx.x * 8 + (threadIdx.x >> 5);
    const int lane = threadIdx.x & 31;
    if (d >= N) return;

    const int* off = g_off + r * (N + 1);
    const int beg = off[d], end = off[d + 1];

    const int a = lane >> 3;
    const float fbv = fb[0];
    const float abr = ab[r];
    const float p2d = g_p2[d];
    const float qdv = g_qd[((size_t)r * N + d) * 4 + a];

    float acc[8];
#pragma unroll
    for (int i = 0; i < 8; i++) acc[i] = 0.f;
    float den = 0.f;

    const int* esrc = g_esrc + (size_t)r * E;
    const float* qsr = g_qs + (size_t)r * N * 4;
    const float* hwr = g_hw + (size_t)r * N * HD;

    for (int j = beg; j < end; j++) {
        int s = __ldg(esrc + j);
        float score = g_p1[s] + p2d + fbv;
        float sgn = (score > 0.f) ? 1.f : ((score < 0.f) ? -1.f : 0.f);
        float x = sgn * qsr[s * 4 + a] + qdv + abr;
        float alpha = (x > 0.f) ? x : 0.01f * x;
        float ex = expf(alpha);
        den += ex;
        float v = ex * sgn;
        const float4* hrow = reinterpret_cast<const float4*>(hwr + (size_t)s * HD) + lane * 2;
        float4 h0 = hrow[0];
        float4 h1 = hrow[1];
        acc[0] = fmaf(v, h0.x, acc[0]); acc[1] = fmaf(v, h0.y, acc[1]);
        acc[2] = fmaf(v, h0.z, acc[2]); acc[3] = fmaf(v, h0.w, acc[3]);
        acc[4] = fmaf(v, h1.x, acc[4]); acc[5] = fmaf(v, h1.y, acc[5]);
        acc[6] = fmaf(v, h1.z, acc[6]); acc[7] = fmaf(v, h1.w, acc[7]);
    }

    float sc = (den > 0.f) ? (1.f / den) : 0.f;
    float4 o0 = make_float4(acc[0] * sc, acc[1] * sc, acc[2] * sc, acc[3] * sc);
    float4 o1 = make_float4(acc[4] * sc, acc[5] * sc, acc[6] * sc, acc[7] * sc);
    float* out = g_num + (size_t)d * (RELS * HD) + r * HD + lane * 8;
    *reinterpret_cast<float4*>(out)     = o0;
    *reinterpret_cast<float4*>(out + 4) = o1;
}

// ---------------- launch ----------------
extern "C" void kernel_launch(void* const* d_in, const int* in_sizes, int n_in,
                              void* d_out, int out_size)
{
    const float* h    = (const float*)d_in[0];
    const float* dW   = (const float*)d_in[1];
    const float* db   = (const float*)d_in[2];
    const float* fW   = (const float*)d_in[3];
    const float* fb   = (const float*)d_in[4];
    const float* wW   = (const float*)d_in[5];
    const float* wb   = (const float*)d_in[6];
    const float* aW   = (const float*)d_in[7];
    const float* ab   = (const float*)d_in[8];
    const float* linW = (const float*)d_in[9];
    const float* linb = (const float*)d_in[10];
    const int*   src  = (const int*)d_in[11];
    const int*   dst  = (const int*)d_in[12];

    const int N = in_sizes[0] / KIN;        // 50000
    const int E = in_sizes[11] / RELS;      // 300000
    const int tiles = (N + BM - 1) / BM;    // 391

    float *p_hw, *p_num;
    cudaGetSymbolAddress((void**)&p_hw,  g_hw);
    cudaGetSymbolAddress((void**)&p_num, g_num);

    // prep: folded projections, packed B planes, per-node scalars
    prep_U_kernel<<<32, 128>>>(dW, fW, wW, aW);
    prep_Uc_kernel<<<1, 1024>>>(db, fW, wb, aW);
    pack_B_kernel<<<(NN * BKTOT + 255) / 256, 256>>>(wW, linW);
    node_scalars_kernel<<<(N + 63) / 64, 256>>>(h, N);

    // CSR build
    zero_cnt_kernel<<<(RELS * N + 255) / 256, 256>>>(RELS * N);
    {
        dim3 egrid((E + 255) / 256, RELS);
        count_kernel<<<egrid, 256>>>(dst, E, N);
        scan_kernel<<<RELS, 1024>>>(N);
        scatter_kernel<<<egrid, 256>>>(src, dst, E, N);
    }

    // hw_r = h @ wW[r] + wb[r]  — HMMA split-bf16, z = relation (k-window r*128)
    {
        dim3 ggrid(NN / BN, tiles, RELS);   // (4, 391, 3)
        mma_gemm_kernel<<<ggrid, 256>>>(
            h, wb, p_hw, N, KIN, /*kb0=*/0, /*kzStride=*/KIN,
            /*biasStride=*/HD, /*cStride=*/(size_t)N * HD);
    }

    // per-destination gather (fused softmax + aggregate + normalize)
    {
        dim3 ggrid((N + 7) / 8, RELS);
        gather_kernel<<<ggrid, 256>>>(fb, ab, E, N);
    }

    // out = num @ linW + linb  — HMMA split-bf16, K=768 (k-window base 384)
    {
        dim3 ggrid(NN / BN, tiles, 1);
        mma_gemm_kernel<<<ggrid, 256>>>(
            p_num, linb, (float*)d_out, N, RELS * HD, /*kb0=*/384, /*kzStride=*/0,
            /*biasStride=*/0, /*cStride=*/0);
    }
}

// round 17
// speedup vs baseline: 1.9752x; 1.1499x over previous
#include <cuda_runtime.h>
#include <cuda_bf16.h>
#include <cstdint>

#define RELS 3
#define NMAX 50000
#define NPAD 50048    // NMAX rounded up to BM so GEMM tail rows stay in-bounds
#define EMAX 300000
#define HD   256      // H = HF*AH
#define KIN  128      // in_feats
#define NN   256      // GEMM output width
#define BKTOT 1152    // packed B row length: 3*128 (wW) + 768 (linW)

// ---------------- scratch (static device globals; no allocation) ----------------
__device__ float g_hw  [(size_t)RELS * NPAD * HD];   // fp32, read by gather
__device__ float g_p1  [NMAX];
__device__ float g_p2  [NMAX];
__device__ float g_qs  [(size_t)RELS * NMAX * 4];
__device__ float g_qd  [(size_t)RELS * NMAX * 4];
__device__ float g_U   [32 * KIN];
__device__ float g_Uc  [32];
// CSR scratch
__device__ int g_cnt [RELS * NMAX];
__device__ int g_cur [RELS * NMAX];
__device__ int g_off [RELS * (NMAX + 1)];
__device__ int g_esrc[(size_t)RELS * EMAX];
// packed B: n-major [NN][BKTOT], bf16 hi and lo planes
__device__ __align__(16) __nv_bfloat16 g_Bh[(size_t)NN * BKTOT];
__device__ __align__(16) __nv_bfloat16 g_Bl[(size_t)NN * BKTOT];
// packed A planes: h (k=128) and num (k=768), bf16 hi/lo
__device__ __align__(16) __nv_bfloat16 g_hbh [(size_t)NPAD * KIN];
__device__ __align__(16) __nv_bfloat16 g_hbl [(size_t)NPAD * KIN];
__device__ __align__(16) __nv_bfloat16 g_numh[(size_t)NPAD * RELS * HD];
__device__ __align__(16) __nv_bfloat16 g_numl[(size_t)NPAD * RELS * HD];

// ---------------- helpers ----------------
__device__ __forceinline__ uint32_t smem_to_u32(const void* p) {
    uint32_t a;
    asm("{ .reg .u64 t; cvta.to.shared.u64 t, %1; cvt.u32.u64 %0, t; }" : "=r"(a) : "l"(p));
    return a;
}
__device__ __forceinline__ void cp16(uint32_t dst, const void* src) {
    asm volatile("cp.async.cg.shared.global [%0], [%1], 16;" :: "r"(dst), "l"(src));
}
__device__ __forceinline__ void mma_bf16(float* c, uint32_t a0, uint32_t a1,
                                         uint32_t a2, uint32_t a3,
                                         uint32_t b0, uint32_t b1) {
    asm volatile("mma.sync.aligned.m16n8k16.row.col.f32.bf16.bf16.f32 "
                 "{%0,%1,%2,%3}, {%4,%5,%6,%7}, {%8,%9}, {%0,%1,%2,%3};"
                 : "+f"(c[0]), "+f"(c[1]), "+f"(c[2]), "+f"(c[3])
                 : "r"(a0), "r"(a1), "r"(a2), "r"(a3), "r"(b0), "r"(b1));
}
// split x,y to bf16 hi (returned packed) and lo (packed to lopack)
__device__ __forceinline__ uint32_t bfsplit2(float x, float y, uint32_t& lopack) {
    __nv_bfloat16 hx = __float2bfloat16(x), hy = __float2bfloat16(y);
    __nv_bfloat16 lx = __float2bfloat16(x - __bfloat162float(hx));
    __nv_bfloat16 ly = __float2bfloat16(y - __bfloat162float(hy));
    uint16_t a = *reinterpret_cast<uint16_t*>(&hx), b = *reinterpret_cast<uint16_t*>(&hy);
    uint16_t c = *reinterpret_cast<uint16_t*>(&lx), d = *reinterpret_cast<uint16_t*>(&ly);
    lopack = ((uint32_t)d << 16) | c;
    return ((uint32_t)b << 16) | a;
}

// =====================================================================
// Pack B (wW / linW) once into bf16 hi/lo planes, n-major [256][1152]
// =====================================================================
__global__ void pack_B_kernel(const float* __restrict__ wW, const float* __restrict__ linW)
{
    int idx = blockIdx.x * blockDim.x + threadIdx.x;
    if (idx >= NN * BKTOT) return;
    int n = idx / BKTOT;
    int c = idx - n * BKTOT;
    float v;
    if (c < 384) v = wW[(size_t)c * NN + n];
    else         v = linW[(size_t)(c - 384) * NN + n];
    __nv_bfloat16 hi = __float2bfloat16(v);
    g_Bh[(size_t)n * BKTOT + c] = hi;
    g_Bl[(size_t)n * BKTOT + c] = __float2bfloat16(v - __bfloat162float(hi));
}

// Pack A = h into bf16 hi/lo planes
__global__ void pack_A_kernel(const float* __restrict__ h, int total)
{
    int i = blockIdx.x * blockDim.x + threadIdx.x;
    if (i >= total) return;
    float v = h[i];
    __nv_bfloat16 hi = __float2bfloat16(v);
    g_hbh[i] = hi;
    g_hbl[i] = __float2bfloat16(v - __bfloat162float(hi));
}

// =====================================================================
// HMMA GEMM, cp.async double-buffered: C = A @ B + bias.
// A given as bf16 hi/lo planes [*, K]; B = g_Bh/g_Bl window at
// kbase = kb0 + z*kzStride. BM=128, BN=64, BK=32, 256 threads.
// Smem: 2 stages x { Ah[128][40], Al[128][40], Bh[64][40], Bl[64][40] }.
// =====================================================================
#define BM 128
#define BN 64
#define BK 32
#define STG_BYTES 30720   // (128+64)*80*2 planes
#define SM_DYN (2 * STG_BYTES)

__global__ __launch_bounds__(256, 2) void mma_gemm_kernel(
    const __nv_bfloat16* __restrict__ Ah, const __nv_bfloat16* __restrict__ Al,
    const float* __restrict__ bias, float* __restrict__ C,
    int M, int K, int kb0, int kzStride, size_t biasStride, size_t cStride)
{
    extern __shared__ char sm[];
    const uint32_t smb = smem_to_u32(sm);
    const int tid  = threadIdx.x;
    const int lane = tid & 31, wid = tid >> 5;
    const int bm = blockIdx.y * BM;
    const int bn = blockIdx.x * BN;
    const int z  = blockIdx.z;
    const int kbase = kb0 + z * kzStride;

    bias += (size_t)z * biasStride;
    C    += (size_t)z * cStride;

    const int wm  = (wid >> 1) * 32;
    const int wn  = (wid & 1) * 32;
    const int grp = lane >> 2;
    const int tig = lane & 3;

    float acc[2][4][4];
#pragma unroll
    for (int mt = 0; mt < 2; mt++)
#pragma unroll
        for (int nt = 0; nt < 4; nt++)
#pragma unroll
            for (int q = 0; q < 4; q++) acc[mt][nt][q] = 0.f;

    // stage issue: A planes (512 chunks each), B planes (256 chunks each)
    auto issue = [&](int s, int k0) {
        uint32_t sb = smb + (uint32_t)s * STG_BYTES;
#pragma unroll
        for (int j = 0; j < 2; j++) {
            int i   = tid + j * 256;        // 0..511
            int row = i >> 2;
            int seg = (i & 3) << 3;         // 0,8,16,24 elements
            size_t src = (size_t)(bm + row) * K + k0 + seg;
            cp16(sb + row * 80 + seg * 2, Ah + src);
            cp16(sb + 10240 + row * 80 + seg * 2, Al + src);
        }
        {
            int row = tid >> 2;
            int seg = (tid & 3) << 3;
            size_t src = (size_t)(bn + row) * BKTOT + kbase + k0 + seg;
            cp16(sb + 20480 + row * 80 + seg * 2, g_Bh + src);
            cp16(sb + 25600 + row * 80 + seg * 2, g_Bl + src);
        }
        asm volatile("cp.async.commit_group;" ::: "memory");
    };

    const int nk = K / BK;
    issue(0, 0);
    for (int ik = 0; ik < nk; ik++) {
        bool more = (ik + 1) < nk;
        if (more) issue((ik + 1) & 1, (ik + 1) * BK);
        if (more) asm volatile("cp.async.wait_group 1;" ::: "memory");
        else      asm volatile("cp.async.wait_group 0;" ::: "memory");
        __syncthreads();

        const char* base = sm + (ik & 1) * STG_BYTES;
#pragma unroll
        for (int ks = 0; ks < 2; ks++) {
            const int kb32 = ks * 8;
            uint32_t ah[2][4], al[2][4];
#pragma unroll
            for (int mt = 0; mt < 2; mt++) {
                int r0 = wm + mt * 16 + grp;
                const uint32_t* p0 = reinterpret_cast<const uint32_t*>(base + r0 * 80);
                const uint32_t* p1 = reinterpret_cast<const uint32_t*>(base + (r0 + 8) * 80);
                const uint32_t* q0 = reinterpret_cast<const uint32_t*>(base + 10240 + r0 * 80);
                const uint32_t* q1 = reinterpret_cast<const uint32_t*>(base + 10240 + (r0 + 8) * 80);
                ah[mt][0] = p0[kb32 + tig];     ah[mt][1] = p1[kb32 + tig];
                ah[mt][2] = p0[kb32 + tig + 4]; ah[mt][3] = p1[kb32 + tig + 4];
                al[mt][0] = q0[kb32 + tig];     al[mt][1] = q1[kb32 + tig];
                al[mt][2] = q0[kb32 + tig + 4]; al[mt][3] = q1[kb32 + tig + 4];
            }
            uint32_t bh[4][2], bl[4][2];
#pragma unroll
            for (int nt = 0; nt < 4; nt++) {
                int n = wn + nt * 8 + grp;
                const uint32_t* p = reinterpret_cast<const uint32_t*>(base + 20480 + n * 80);
                const uint32_t* q = reinterpret_cast<const uint32_t*>(base + 25600 + n * 80);
                bh[nt][0] = p[kb32 + tig]; bh[nt][1] = p[kb32 + tig + 4];
                bl[nt][0] = q[kb32 + tig]; bl[nt][1] = q[kb32 + tig + 4];
            }
#pragma unroll
            for (int mt = 0; mt < 2; mt++)
#pragma unroll
                for (int nt = 0; nt < 4; nt++) {
                    mma_bf16(acc[mt][nt], ah[mt][0], ah[mt][1], ah[mt][2], ah[mt][3],
                             bh[nt][0], bh[nt][1]);
                    mma_bf16(acc[mt][nt], ah[mt][0], ah[mt][1], ah[mt][2], ah[mt][3],
                             bl[nt][0], bl[nt][1]);
                    mma_bf16(acc[mt][nt], al[mt][0], al[mt][1], al[mt][2], al[mt][3],
                             bh[nt][0], bh[nt][1]);
                }
        }
        __syncthreads();
    }

#pragma unroll
    for (int mt = 0; mt < 2; mt++) {
        int row0 = bm + wm + mt * 16 + grp;
#pragma unroll
        for (int nt = 0; nt < 4; nt++) {
            int col = bn + wn + nt * 8 + tig * 2;
            float2 bb = *reinterpret_cast<const float2*>(bias + col);
            if (row0 < M) {
                float2 o = make_float2(acc[mt][nt][0] + bb.x, acc[mt][nt][1] + bb.y);
                *reinterpret_cast<float2*>(C + (size_t)row0 * NN + col) = o;
            }
            if (row0 + 8 < M) {
                float2 o = make_float2(acc[mt][nt][2] + bb.x, acc[mt][nt][3] + bb.y);
                *reinterpret_cast<float2*>(C + (size_t)(row0 + 8) * NN + col) = o;
            }
        }
    }
}

// =====================================================================
// prep kernels (unchanged, passing)
// =====================================================================
__global__ void prep_U_kernel(const float* __restrict__ dW, const float* __restrict__ fW,
                              const float* __restrict__ wW, const float* __restrict__ aW)
{
    int col = blockIdx.x;
    int k   = threadIdx.x;
    float s = 0.f;
    if (col < 2) {
        const float* dwr = dW + (size_t)k * HD;
        for (int j = 0; j < HD; j++) {
            float f = (col == 0) ? (fW[j] + fW[512 + j]) : (fW[256 + j] - fW[512 + j]);
            s += dwr[j] * f;
        }
    } else if (col < 26) {
        int c = col - 2;
        int half = 0;
        if (c >= 12) { c -= 12; half = 1; }
        int r = c >> 2, a = c & 3;
        const float* wwr = wW + ((size_t)r * KIN + k) * HD + a * 64;
        const float* awr = aW + r * 128 + half * 64;
        for (int j = 0; j < 64; j++) s += wwr[j] * awr[j];
    }
    g_U[col * KIN + k] = s;
}

__global__ void prep_Uc_kernel(const float* __restrict__ db, const float* __restrict__ fW,
                               const float* __restrict__ wb, const float* __restrict__ aW)
{
    int col  = threadIdx.x >> 5;
    int lane = threadIdx.x & 31;
    float s = 0.f;
    if (col < 2) {
        for (int j = lane; j < HD; j += 32) {
            float f = (col == 0) ? (fW[j] + fW[512 + j]) : (fW[256 + j] - fW[512 + j]);
            s += db[j] * f;
        }
    } else if (col < 26) {
        int c = col - 2;
        int half = 0;
        if (c >= 12) { c -= 12; half = 1; }
        int r = c >> 2, a = c & 3;
        for (int j = lane; j < 64; j += 32)
            s += wb[r * HD + a * 64 + j] * aW[r * 128 + half * 64 + j];
    }
#pragma unroll
    for (int o = 16; o > 0; o >>= 1) s += __shfl_xor_sync(0xFFFFFFFFu, s, o);
    if (lane == 0) g_Uc[col] = s;
}

// =====================================================================
// Node scalars (unchanged from R16 — passing)
// =====================================================================
__global__ __launch_bounds__(256) void node_scalars_kernel(const float* __restrict__ h, int N)
{
    __shared__ float sh[64][KIN];
    __shared__ float su[KIN][32];
    const int tid   = threadIdx.x;
    const int node0 = blockIdx.x * 64;

    for (int i = tid; i < 32 * KIN; i += 256) {
        int col = i >> 7, k = i & 127;
        su[k][col] = g_U[i];
    }
    for (int i = tid; i < 64 * 32; i += 256) {
        int row = i >> 5, c4 = i & 31;
        int n = node0 + row;
        float4 v = make_float4(0.f, 0.f, 0.f, 0.f);
        if (n < N) v = *reinterpret_cast<const float4*>(h + (size_t)n * KIN + c4 * 4);
        *reinterpret_cast<float4*>(&sh[row][c4 * 4]) = v;
    }
    __syncthreads();

    const int tx = tid & 31;
    const int ty = tid >> 5;
    float acc[8];
#pragma unroll
    for (int i = 0; i < 8; i++) acc[i] = 0.f;

    for (int k4 = 0; k4 < 32; k4++) {
        float u0 = su[k4 * 4 + 0][tx];
        float u1 = su[k4 * 4 + 1][tx];
        float u2 = su[k4 * 4 + 2][tx];
        float u3 = su[k4 * 4 + 3][tx];
#pragma unroll
        for (int i = 0; i < 8; i++) {
            float4 hv = *reinterpret_cast<const float4*>(&sh[ty * 8 + i][k4 * 4]);
            acc[i] += hv.x * u0 + hv.y * u1 + hv.z * u2 + hv.w * u3;
        }
    }

    if (tx < 26) {
        float uc = g_Uc[tx];
#pragma unroll
        for (int i = 0; i < 8; i++) {
            int n = node0 + ty * 8 + i;
            if (n >= N) break;
            float val = acc[i] + uc;
            if (tx == 0)      g_p1[n] = val;
            else if (tx == 1) g_p2[n] = val;
            else if (tx < 14) {
                int c = tx - 2, r = c >> 2, a = c & 3;
                g_qs[((size_t)r * N + n) * 4 + a] = val;
            } else {
                int c = tx - 14, r = c >> 2, a = c & 3;
                g_qd[((size_t)r * N + n) * 4 + a] = val;
            }
        }
    }
}

// ---------------- CSR build (unchanged, passing) ----------------
__global__ void zero_cnt_kernel(int n) {
    int i = blockIdx.x * blockDim.x + threadIdx.x;
    if (i < n) g_cnt[i] = 0;
}
__global__ void count_kernel(const int* __restrict__ dst, int E, int N) {
    int r = blockIdx.y;
    int e = blockIdx.x * blockDim.x + threadIdx.x;
    if (e >= E) return;
    int d = __ldg(dst + (size_t)r * E + e);
    atomicAdd(g_cnt + r * N + d, 1);
}
__global__ __launch_bounds__(1024) void scan_kernel(int N) {
    const int r    = blockIdx.x;
    const int tid  = threadIdx.x;
    const int lane = tid & 31, wid = tid >> 5;
    __shared__ int wsum[32];
    __shared__ int carry;
    if (tid == 0) carry = 0;
    __syncthreads();
    const int* cnt = g_cnt + r * N;
    int* off = g_off + r * (N + 1);
    int* cur = g_cur + r * N;
    for (int base = 0; base < N; base += 1024) {
        int i = base + tid;
        int v = (i < N) ? cnt[i] : 0;
        int x = v;
#pragma unroll
        for (int o = 1; o < 32; o <<= 1) {
            int y = __shfl_up_sync(0xFFFFFFFFu, x, o);
            if (lane >= o) x += y;
        }
        if (lane == 31) wsum[wid] = x;
        __syncthreads();
        if (wid == 0) {
            int y = wsum[lane];
#pragma unroll
            for (int o = 1; o < 32; o <<= 1) {
                int z = __shfl_up_sync(0xFFFFFFFFu, y, o);
                if (lane >= o) y += z;
            }
            wsum[lane] = y;
        }
        __syncthreads();
        int prefix = (wid > 0) ? wsum[wid - 1] : 0;
        int c = carry;
        if (i < N) {
            int val = c + prefix + x - v;
            off[i] = val;
            cur[i] = val;
        }
        int total = wsum[31];
        __syncthreads();
        if (tid == 0) carry = c + total;
        __syncthreads();
    }
    if (tid == 0) off[N] = carry;
}
__global__ void scatter_kernel(const int* __restrict__ src, const int* __restrict__ dst,
                               int E, int N) {
    int r = blockIdx.y;
    int e = blockIdx.x * blockDim.x + threadIdx.x;
    if (e >= E) return;
    int d = __ldg(dst + (size_t)r * E + e);
    int pos = atomicAdd(g_cur + r * N + d, 1);
    g_esrc[(size_t)r * E + pos] = __ldg(src + (size_t)r * E + e);
}

// ---------------- gather: writes num as bf16 hi/lo planes ----------------
__global__ __launch_bounds__(256) void gather_kernel(
    const float* __restrict__ fb, const float* __restrict__ ab, int E, int N)
{
    const int r    = blockIdx.y;
    const int d    = blockIdx.x * 8 + (threadIdx.x >> 5);
    const int lane = threadIdx.x & 31;
    if (d >= N) return;

    const int* off = g_off + r * (N + 1);
    const int beg = off[d], end = off[d + 1];

    const int a = lane >> 3;
    const float fbv = fb[0];
    const float abr = ab[r];
    const float p2d = g_p2[d];
    const float qdv = g_qd[((size_t)r * N + d) * 4 + a];

    float acc[8];
#pragma unroll
    for (int i = 0; i < 8; i++) acc[i] = 0.f;
    float den = 0.f;

    const int* esrc = g_esrc + (size_t)r * E;
    const float* qsr = g_qs + (size_t)r * N * 4;
    const float* hwr = g_hw + (size_t)r * NPAD * HD;

    for (int j = beg; j < end; j++) {
        int s = __ldg(esrc + j);
        float score = g_p1[s] + p2d + fbv;
        float sgn = (score > 0.f) ? 1.f : ((score < 0.f) ? -1.f : 0.f);
        float x = sgn * qsr[s * 4 + a] + qdv + abr;
        float alpha = (x > 0.f) ? x : 0.01f * x;
        float ex = expf(alpha);
        den += ex;
        float v = ex * sgn;
        const float4* hrow = reinterpret_cast<const float4*>(hwr + (size_t)s * HD) + lane * 2;
        float4 h0 = hrow[0];
        float4 h1 = hrow[1];
        acc[0] = fmaf(v, h0.x, acc[0]); acc[1] = fmaf(v, h0.y, acc[1]);
        acc[2] = fmaf(v, h0.z, acc[2]); acc[3] = fmaf(v, h0.w, acc[3]);
        acc[4] = fmaf(v, h1.x, acc[4]); acc[5] = fmaf(v, h1.y, acc[5]);
        acc[6] = fmaf(v, h1.z, acc[6]); acc[7] = fmaf(v, h1.w, acc[7]);
    }

    float sc = (den > 0.f) ? (1.f / den) : 0.f;
    uint32_t hp[4], lp[4];
#pragma unroll
    for (int q = 0; q < 4; q++)
        hp[q] = bfsplit2(acc[q * 2] * sc, acc[q * 2 + 1] * sc, lp[q]);
    size_t base = (size_t)d * (RELS * HD) + r * HD + lane * 8;
    *reinterpret_cast<uint4*>(g_numh + base) = make_uint4(hp[0], hp[1], hp[2], hp[3]);
    *reinterpret_cast<uint4*>(g_numl + base) = make_uint4(lp[0], lp[1], lp[2], lp[3]);
}

// ---------------- launch ----------------
extern "C" void kernel_launch(void* const* d_in, const int* in_sizes, int n_in,
                              void* d_out, int out_size)
{
    const float* h    = (const float*)d_in[0];
    const float* dW   = (const float*)d_in[1];
    const float* db   = (const float*)d_in[2];
    const float* fW   = (const float*)d_in[3];
    const float* fb   = (const float*)d_in[4];
    const float* wW   = (const float*)d_in[5];
    const float* wb   = (const float*)d_in[6];
    const float* aW   = (const float*)d_in[7];
    const float* ab   = (const float*)d_in[8];
    const float* linW = (const float*)d_in[9];
    const float* linb = (const float*)d_in[10];
    const int*   src  = (const int*)d_in[11];
    const int*   dst  = (const int*)d_in[12];

    const int N = in_sizes[0] / KIN;        // 50000
    const int E = in_sizes[11] / RELS;      // 300000
    const int tiles = (N + BM - 1) / BM;    // 391

    float* p_hw;
    __nv_bfloat16 *p_hbh, *p_hbl, *p_numh, *p_numl;
    cudaGetSymbolAddress((void**)&p_hw,   g_hw);
    cudaGetSymbolAddress((void**)&p_hbh,  g_hbh);
    cudaGetSymbolAddress((void**)&p_hbl,  g_hbl);
    cudaGetSymbolAddress((void**)&p_numh, g_numh);
    cudaGetSymbolAddress((void**)&p_numl, g_numl);

    cudaFuncSetAttribute(mma_gemm_kernel,
                         cudaFuncAttributeMaxDynamicSharedMemorySize, SM_DYN);

    // prep: folded projections, packed operands, per-node scalars
    prep_U_kernel<<<32, 128>>>(dW, fW, wW, aW);
    prep_Uc_kernel<<<1, 1024>>>(db, fW, wb, aW);
    pack_B_kernel<<<(NN * BKTOT + 255) / 256, 256>>>(wW, linW);
    pack_A_kernel<<<(N * KIN + 255) / 256, 256>>>(h, N * KIN);
    node_scalars_kernel<<<(N + 63) / 64, 256>>>(h, N);

    // CSR build
    zero_cnt_kernel<<<(RELS * N + 255) / 256, 256>>>(RELS * N);
    {
        dim3 egrid((E + 255) / 256, RELS);
        count_kernel<<<egrid, 256>>>(dst, E, N);
        scan_kernel<<<RELS, 1024>>>(N);
        scatter_kernel<<<egrid, 256>>>(src, dst, E, N);
    }

    // hw_r = h @ wW[r] + wb[r]  — pipelined HMMA, z = relation
    {
        dim3 ggrid(NN / BN, tiles, RELS);   // (4, 391, 3)
        mma_gemm_kernel<<<ggrid, 256, SM_DYN>>>(
            p_hbh, p_hbl, wb, p_hw, N, KIN, /*kb0=*/0, /*kzStride=*/KIN,
            /*biasStride=*/HD, /*cStride=*/(size_t)NPAD * HD);
    }

    // per-destination gather (fused softmax + aggregate + normalize -> bf16 planes)
    {
        dim3 ggrid((N + 7) / 8, RELS);
        gather_kernel<<<ggrid, 256>>>(fb, ab, E, N);
    }

    // out = num @ linW + linb  — pipelined HMMA, K=768
    {
        dim3 ggrid(NN / BN, tiles, 1);
        mma_gemm_kernel<<<ggrid, 256, SM_DYN>>>(
            p_numh, p_numl, linb, (float*)d_out, N, RELS * HD,
            /*kb0=*/384, /*kzStride=*/0, /*biasStride=*/0, /*cStride=*/0);
    }
}